// round 3
// baseline (speedup 1.0000x reference)
#include <cuda_runtime.h>
#include <math.h>

#define HWN   16384
#define CC    256
#define BATCH 4
#define CHW   (CC*HWN)
#define SPLITS 8
#define SLAB  (HWN/SPLITS)

// ---------------- scratch (static __device__, no allocations) ----------------
__device__ __align__(16) float d_Sx[BATCH*CC];
__device__ __align__(16) float d_Sxx[BATCH*CC];
__device__ __align__(16) float d_m[BATCH*CC];
__device__ __align__(16) float d_a[BATCH*CC];
__device__ __align__(16) float d_wa[BATCH*CC];
__device__ __align__(16) float d_rp[BATCH*CC];
__device__ __align__(16) float d_Wq[CC*CC];
__device__ __align__(16) float d_Wk[CC*CC];
__device__ __align__(16) float d_Wv[CC*CC];
__device__ __align__(16) float d_btq[CC];
__device__ __align__(16) float d_btk[CC];
__device__ __align__(16) float d_btv[CC];
__device__ __align__(16) float d_Gpart[BATCH*SPLITS*CC*CC];   // 8 MB
__device__ __align__(16) float d_G[BATCH*CC*CC];
__device__ __align__(16) float d_U[BATCH*CC*CC];
__device__ __align__(16) float d_pq[BATCH*CC];
__device__ __align__(16) float d_pk[BATCH*CC];
__device__ __align__(16) float d_sc[BATCH*64*16];
__device__ __align__(16) float d_Smx[BATCH*64*16];
__device__ __align__(16) float d_T[BATCH*CC*CC];
__device__ __align__(16) float d_tv[BATCH*CC];
__device__ __align__(16) float d_E[BATCH*CC*CC];
__device__ __align__(16) float d_F[BATCH*CC*CC];
__device__ __align__(16) float d_g[BATCH*CC];

// ---------------- 1) per-(b,c) sums of x ----------------
__global__ void stats_kernel(const float* __restrict__ x) {
    int bc = blockIdx.x;
    const float4* p = (const float4*)(x + (size_t)bc * HWN);
    float s = 0.f, s2 = 0.f;
    for (int i = threadIdx.x; i < HWN/4; i += 256) {
        float4 v = p[i];
        s  += v.x + v.y + v.z + v.w;
        s2 += v.x*v.x + v.y*v.y + v.z*v.z + v.w*v.w;
    }
    for (int o = 16; o; o >>= 1) {
        s  += __shfl_down_sync(0xffffffffu, s, o);
        s2 += __shfl_down_sync(0xffffffffu, s2, o);
    }
    __shared__ float sh[8][2];
    int w = threadIdx.x >> 5, l = threadIdx.x & 31;
    if (l == 0) { sh[w][0] = s; sh[w][1] = s2; }
    __syncthreads();
    if (threadIdx.x == 0) {
        float S = 0.f, S2 = 0.f;
        for (int i = 0; i < 8; i++) { S += sh[i][0]; S2 += sh[i][1]; }
        d_Sx[bc] = S; d_Sxx[bc] = S2;
    }
}

// ---------------- 2) pack qkv rows into head-contiguous Wq/Wk/Wv + fold gn_bias ----------------
// qkv channel layout: o = h*12 + j ; j in [0,4)=q, [4,8)=k, [8,12)=v. packed p = h*4+d.
__global__ void pack_kernel(const float* __restrict__ qkvw,
                            const float* __restrict__ qkvb,
                            const float* __restrict__ gnb) {
    int rid = blockIdx.x * 128 + threadIdx.x;          // 0..767
    if (rid >= 768) return;
    int sel = rid / 256;
    int p   = rid % 256;
    int h = p >> 2, dd = p & 3;
    int src = h * 12 + sel * 4 + dd;
    const float* wrow = qkvw + src * 256;
    float* dst = (sel == 0 ? d_Wq : (sel == 1 ? d_Wk : d_Wv)) + p * 256;
    float dot = 0.f;
    for (int c = 0; c < 256; c++) {
        float w = wrow[c];
        dst[c] = w;
        dot += w * gnb[c];
    }
    float bt = qkvb[src] + dot;
    if (sel == 0) d_btq[p] = bt; else if (sel == 1) d_btk[p] = bt; else d_btv[p] = bt;
}

// ---------------- 3) group stats -> per-channel mean/scale, row sums ----------------
__global__ void groupstats_kernel(const float* __restrict__ gnw) {
    int t = threadIdx.x;               // 0..127 = (b,g)
    if (t >= 128) return;
    int b = t >> 5, g = t & 31;
    float s = 0.f, s2 = 0.f;
    for (int c8 = 0; c8 < 8; c8++) {
        int idx = b * 256 + g * 8 + c8;
        s += d_Sx[idx]; s2 += d_Sxx[idx];
    }
    const float n = 8.f * (float)HWN;      // 131072
    float mean = s / n;
    float var  = (s2 - n * mean * mean) / (n - 1.f);
    float a = rsqrtf(var + 1e-5f);
    for (int c8 = 0; c8 < 8; c8++) {
        int c = g * 8 + c8;
        int idx = b * 256 + c;
        d_m[idx] = mean;
        d_a[idx] = a;
        float wa = gnw[c] * a;
        d_wa[idx] = wa;
        d_rp[idx] = wa * (d_Sx[idx] - (float)HWN * mean);
    }
}

// ---------------- 4) Gram partials: Gx = x xT (per batch, split-K over n) ----------------
__global__ void gram_kernel(const float* __restrict__ x) {
    int b = blockIdx.z, split = blockIdx.y, t = blockIdx.x;
    int ti = t >> 2, tj = t & 3;
    const float* xb = x + (size_t)b * CHW;
    int i0 = ti * 64, j0 = tj * 64;
    __shared__ float As[16][64];
    __shared__ float Bs[16][64];
    int tid = threadIdx.x;
    int tx = tid & 15, ty = tid >> 4;
    int lr = tid >> 2, ls = tid & 3;
    float acc[4][4] = {};
    int kbase = split * SLAB;
    for (int k0 = kbase; k0 < kbase + SLAB; k0 += 16) {
        float4 av = *(const float4*)&xb[(size_t)(i0 + lr) * HWN + k0 + ls * 4];
        As[ls*4+0][lr] = av.x; As[ls*4+1][lr] = av.y; As[ls*4+2][lr] = av.z; As[ls*4+3][lr] = av.w;
        float4 bv = *(const float4*)&xb[(size_t)(j0 + lr) * HWN + k0 + ls * 4];
        Bs[ls*4+0][lr] = bv.x; Bs[ls*4+1][lr] = bv.y; Bs[ls*4+2][lr] = bv.z; Bs[ls*4+3][lr] = bv.w;
        __syncthreads();
#pragma unroll
        for (int kk = 0; kk < 16; kk++) {
            float4 a4 = *(const float4*)&As[kk][ty * 4];
            float4 b4 = *(const float4*)&Bs[kk][tx * 4];
            float avv[4] = {a4.x, a4.y, a4.z, a4.w};
            float bvv[4] = {b4.x, b4.y, b4.z, b4.w};
#pragma unroll
            for (int i = 0; i < 4; i++)
#pragma unroll
                for (int j = 0; j < 4; j++)
                    acc[i][j] += avv[i] * bvv[j];
        }
        __syncthreads();
    }
    float* gp = d_Gpart + (size_t)(b * SPLITS + split) * 65536;
#pragma unroll
    for (int i = 0; i < 4; i++) {
        int row = i0 + ty * 4 + i;
        float4 v; v.x = acc[i][0]; v.y = acc[i][1]; v.z = acc[i][2]; v.w = acc[i][3];
        *(float4*)&gp[row * 256 + j0 + tx * 4] = v;
    }
}

// ---------------- 5) reduce partials + GN corrections -> G' ----------------
__global__ void reduceG_kernel() {
    int e = blockIdx.x * 256 + threadIdx.x;    // 0..262143
    int b = e >> 16;
    int ij = e & 65535;
    int i = ij >> 8, j = ij & 255;
    float sum = 0.f;
    size_t base = (size_t)b * SPLITS * 65536 + ij;
    for (int s = 0; s < SPLITS; s++) sum += d_Gpart[base + (size_t)s * 65536];
    int bi = b * 256 + i, bj = b * 256 + j;
    float g = d_wa[bi] * d_wa[bj] *
              (sum - d_m[bi] * d_Sx[bj] - d_m[bj] * d_Sx[bi] + (float)HWN * d_m[bi] * d_m[bj]);
    d_G[b * 65536 + ij] = g;
}

// ---------------- generic 64x64-tile GEMM (M=256, K=256) ----------------
// MODE 0: U = Wq @ G'        (N=256)
// MODE 1: E = out_w @ T      (N=256)
// MODE 2: out = F @ x + g + x (N=16384, epilogue)
template<int MODE>
__global__ void gemm64(const float* __restrict__ Aext,
                       const float* __restrict__ Bext,
                       float* __restrict__ Cext) {
    constexpr int N = (MODE == 2) ? HWN : 256;
    int b = blockIdx.z;
    const float* A; const float* B; float* Cp;
    const float* bias = nullptr; const float* skip = nullptr;
    if (MODE == 0) { A = d_Wq;                 B = d_G + b * 65536;        Cp = d_U + b * 65536; }
    else if (MODE == 1) { A = Aext;            B = d_T + b * 65536;        Cp = d_E + b * 65536; }
    else { A = d_F + b * 65536; B = Bext + (size_t)b * CHW; Cp = Cext + (size_t)b * CHW;
           bias = d_g + b * 256; skip = B; }

    __shared__ float As[16][64];
    __shared__ float Bs[16][64];
    int m0 = blockIdx.x * 64, n0 = blockIdx.y * 64;
    int tid = threadIdx.x;
    int tx = tid & 15, ty = tid >> 4;
    int ar = tid >> 2, asg = tid & 3;
    int br = tid >> 4, bc = tid & 15;
    float acc[4][4] = {};
    for (int k0 = 0; k0 < 256; k0 += 16) {
        float4 av = *(const float4*)&A[(m0 + ar) * 256 + k0 + asg * 4];
        As[asg*4+0][ar] = av.x; As[asg*4+1][ar] = av.y; As[asg*4+2][ar] = av.z; As[asg*4+3][ar] = av.w;
        float4 bv = *(const float4*)&B[(size_t)(k0 + br) * N + n0 + bc * 4];
        *(float4*)&Bs[br][bc * 4] = bv;
        __syncthreads();
#pragma unroll
        for (int kk = 0; kk < 16; kk++) {
            float4 a4 = *(const float4*)&As[kk][ty * 4];
            float4 b4 = *(const float4*)&Bs[kk][tx * 4];
            float avv[4] = {a4.x, a4.y, a4.z, a4.w};
            float bvv[4] = {b4.x, b4.y, b4.z, b4.w};
#pragma unroll
            for (int i = 0; i < 4; i++)
#pragma unroll
                for (int j = 0; j < 4; j++)
                    acc[i][j] += avv[i] * bvv[j];
        }
        __syncthreads();
    }
#pragma unroll
    for (int i = 0; i < 4; i++) {
        int m = m0 + ty * 4 + i;
        float4 v; v.x = acc[i][0]; v.y = acc[i][1]; v.z = acc[i][2]; v.w = acc[i][3];
        if (MODE == 2) {
            float bi = bias[m];
            float4 sk = *(const float4*)&skip[(size_t)m * N + n0 + tx * 4];
            v.x += bi + sk.x; v.y += bi + sk.y; v.z += bi + sk.z; v.w += bi + sk.w;
        }
        *(float4*)&Cp[(size_t)m * N + n0 + tx * 4] = v;
    }
}

// ---------------- 6) p-vectors: pq/pk = Wq/Wk @ r' ----------------
__global__ void pvec_kernel() {
    int rid = blockIdx.x * 128 + threadIdx.x;   // 0..2047
    if (rid >= 2048) return;
    int b = rid / 512;
    int q = rid % 512;
    int sel = q / 256, p = q % 256;
    const float* w = (sel ? d_Wk : d_Wq) + p * 256;
    const float* r = d_rp + b * 256;
    float s = 0.f;
    for (int c = 0; c < 256; c++) s += w[c] * r[c];
    (sel ? d_pk : d_pq)[b * 256 + p] = s;
}

// ---------------- 7) raw scores: (U Wk^T + bias corrections)/2 ----------------
__global__ void scores_kernel() {
    int bi = blockIdx.x;
    int b = bi >> 6, h = bi & 63;
    int tid = threadIdx.x;
    int pair = tid >> 4, l = tid & 15;
    int dd = pair >> 2, ee = pair & 3;
    int pU = h * 4 + dd, pK = h * 4 + ee;
    const float* u  = d_U + (size_t)b * 65536 + pU * 256;
    const float* wk = d_Wk + pK * 256;
    float s = 0.f;
    for (int c = l; c < 256; c += 16) s += u[c] * wk[c];
    for (int o = 8; o; o >>= 1) s += __shfl_down_sync(0xffffffffu, s, o, 16);
    if (l == 0) {
        s += d_pq[b * 256 + pU] * d_btk[pK]
           + d_btq[pU] * d_pk[b * 256 + pK]
           + (float)HWN * d_btq[pU] * d_btk[pK];
        d_sc[(b * 64 + h) * 16 + pair] = 0.5f * s;
    }
}

// ---------------- 8) softmax over heads axis ----------------
__global__ void softmax_kernel() {
    int b = blockIdx.x;
    int w = threadIdx.x >> 5;     // pair 0..15
    int l = threadIdx.x & 31;     // heads l and l+32
    float v0 = d_sc[((b * 64 + l) << 4) + w];
    float v1 = d_sc[((b * 64 + l + 32) << 4) + w];
    float mx = fmaxf(v0, v1);
    for (int o = 16; o; o >>= 1) mx = fmaxf(mx, __shfl_xor_sync(0xffffffffu, mx, o));
    float e0 = expf(v0 - mx), e1 = expf(v1 - mx);
    float s = e0 + e1;
    for (int o = 16; o; o >>= 1) s += __shfl_xor_sync(0xffffffffu, s, o);
    d_Smx[((b * 64 + l) << 4) + w] = e0 / s;
    d_Smx[((b * 64 + l + 32) << 4) + w] = e1 / s;
}

// ---------------- 9) T = BlockDiag(S) Wv diag(gnw), tv = BD(S) btv ----------------
__global__ void t_kernel(const float* __restrict__ gnw) {
    int bi = blockIdx.x;
    int b = bi >> 6, h = bi & 63;
    int c = threadIdx.x;
    __shared__ float Ssh[16];
    if (c < 16) Ssh[c] = d_Smx[(b * 64 + h) * 16 + c];
    __syncthreads();
    float w0 = d_Wv[(h*4+0)*256 + c];
    float w1 = d_Wv[(h*4+1)*256 + c];
    float w2 = d_Wv[(h*4+2)*256 + c];
    float w3 = d_Wv[(h*4+3)*256 + c];
    float gc = gnw[c];
#pragma unroll
    for (int dd = 0; dd < 4; dd++) {
        float s = Ssh[dd*4+0]*w0 + Ssh[dd*4+1]*w1 + Ssh[dd*4+2]*w2 + Ssh[dd*4+3]*w3;
        d_T[((size_t)b * 256 + h * 4 + dd) * 256 + c] = gc * s;
    }
    if (c < 4) {
        float tv = 0.f;
        for (int e = 0; e < 4; e++) tv += Ssh[c * 4 + e] * d_btv[h * 4 + e];
        d_tv[b * 256 + h * 4 + c] = tv;
    }
}

// ---------------- 10) fold: F = E diag(a), g = out_b + out_w tv - F m ----------------
__global__ void fold_kernel(const float* __restrict__ outw,
                            const float* __restrict__ outb) {
    int b = blockIdx.x;
    int o = threadIdx.x;
    const float* ow = outw + o * 256;
    float e = outb[o];
    for (int p = 0; p < 256; p++) e += ow[p] * d_tv[b * 256 + p];
    float gacc = 0.f;
    for (int c = 0; c < 256; c++) {
        int idx = (b * 256 + o) * 256 + c;
        float f = d_E[idx] * d_a[b * 256 + c];
        d_F[idx] = f;
        gacc += f * d_m[b * 256 + c];
    }
    d_g[b * 256 + o] = e - gacc;
}

// ---------------- launch ----------------
extern "C" void kernel_launch(void* const* d_in, const int* in_sizes, int n_in,
                              void* d_out, int out_size) {
    const float* x    = (const float*)d_in[0];
    const float* gnw  = (const float*)d_in[1];
    const float* gnb  = (const float*)d_in[2];
    const float* qkvw = (const float*)d_in[3];
    const float* qkvb = (const float*)d_in[4];
    const float* outw = (const float*)d_in[5];
    const float* outb = (const float*)d_in[6];
    float* out = (float*)d_out;

    stats_kernel<<<BATCH * CC, 256>>>(x);
    pack_kernel<<<6, 128>>>(qkvw, qkvb, gnb);
    groupstats_kernel<<<1, 128>>>(gnw);
    gram_kernel<<<dim3(16, SPLITS, BATCH), 256>>>(x);
    reduceG_kernel<<<1024, 256>>>();
    gemm64<0><<<dim3(4, 4, BATCH), 256>>>(nullptr, nullptr, nullptr);
    pvec_kernel<<<16, 128>>>();
    scores_kernel<<<BATCH * 64, 256>>>();
    softmax_kernel<<<BATCH, 512>>>();
    t_kernel<<<BATCH * 64, 256>>>(gnw);
    gemm64<1><<<dim3(4, 4, BATCH), 256>>>(outw, nullptr, nullptr);
    fold_kernel<<<BATCH, 256>>>(outw, outb);
    gemm64<2><<<dim3(4, HWN / 64, BATCH), 256>>>(nullptr, x, out);
}

// round 6
// speedup vs baseline: 1.9810x; 1.9810x over previous
#include <cuda_runtime.h>
#include <cuda_bf16.h>
#include <math.h>
#include <stdint.h>

#define HWN   16384
#define CC    256
#define BATCH 4
#define CHW   (CC*HWN)
#define GSPLITS 16

// ---------------- scratch (static __device__, no allocations) ----------------
__device__ __align__(16) float d_Sx[BATCH*CC];
__device__ __align__(16) float d_Sxx[BATCH*CC];
__device__ __align__(16) float d_m[BATCH*CC];
__device__ __align__(16) float d_a[BATCH*CC];
__device__ __align__(16) float d_wa[BATCH*CC];
__device__ __align__(16) float d_rp[BATCH*CC];
__device__ __align__(16) float d_Wq[CC*CC];
__device__ __align__(16) float d_Wk[CC*CC];
__device__ __align__(16) float d_Wv[CC*CC];
__device__ __align__(16) float d_btq[CC];
__device__ __align__(16) float d_btk[CC];
__device__ __align__(16) float d_btv[CC];
__device__ __align__(16) __nv_bfloat16 d_b1[BATCH*CHW];        // 32 MB
__device__ __align__(16) __nv_bfloat16 d_b2[BATCH*CHW];        // 32 MB
__device__ __align__(16) float d_Gpart[BATCH*GSPLITS*CC*CC];   // 16 MB
__device__ __align__(16) float d_G[BATCH*CC*CC];
__device__ __align__(16) float d_U[BATCH*CC*CC];
__device__ __align__(16) float d_pq[BATCH*CC];
__device__ __align__(16) float d_pk[BATCH*CC];
__device__ __align__(16) float d_sc[BATCH*64*16];
__device__ __align__(16) float d_Smx[BATCH*64*16];
__device__ __align__(16) float d_T[BATCH*CC*CC];
__device__ __align__(16) float d_tv[BATCH*CC];
__device__ __align__(16) float d_E[BATCH*CC*CC];
__device__ __align__(16) __nv_bfloat16 d_F1[BATCH*CC*CC];
__device__ __align__(16) __nv_bfloat16 d_F2[BATCH*CC*CC];
__device__ __align__(16) float d_g[BATCH*CC];

// ---------------- mma / ldmatrix helpers (baseline PTX, sm_80+) ----------------
__device__ __forceinline__ uint32_t smem_u32(const void* p) {
    uint32_t a;
    asm("{ .reg .u64 t; cvta.to.shared.u64 t, %1; cvt.u32.u64 %0, t; }" : "=r"(a) : "l"(p));
    return a;
}
__device__ __forceinline__ void ldm_x4(uint32_t* r, uint32_t addr) {
    asm volatile("ldmatrix.sync.aligned.m8n8.x4.shared.b16 {%0,%1,%2,%3}, [%4];"
                 : "=r"(r[0]), "=r"(r[1]), "=r"(r[2]), "=r"(r[3]) : "r"(addr));
}
__device__ __forceinline__ void ldm_x4_t(uint32_t* r, uint32_t addr) {
    asm volatile("ldmatrix.sync.aligned.m8n8.x4.trans.shared.b16 {%0,%1,%2,%3}, [%4];"
                 : "=r"(r[0]), "=r"(r[1]), "=r"(r[2]), "=r"(r[3]) : "r"(addr));
}
__device__ __forceinline__ void mma_bf16(float* c, const uint32_t* a,
                                         uint32_t b0, uint32_t b1) {
    asm volatile("mma.sync.aligned.m16n8k16.row.col.f32.bf16.bf16.f32 "
                 "{%0,%1,%2,%3}, {%4,%5,%6,%7}, {%8,%9}, {%0,%1,%2,%3};"
                 : "+f"(c[0]), "+f"(c[1]), "+f"(c[2]), "+f"(c[3])
                 : "r"(a[0]), "r"(a[1]), "r"(a[2]), "r"(a[3]), "r"(b0), "r"(b1));
}
// SW for 128B-row tiles (A / gram-B): XOR 16B-chunk idx (bits 4-6) with row%8 (bits 7-9)
#define SWA(o) ((o) ^ (((o) >> 3) & 0x70))
// SW for 256B-row tiles (fgemm B): XOR bits 4-6 with k-row%8 (bits 8-10)
#define SWB(o) ((o) ^ ((((o) >> 8) & 7) << 4))

// ---------------- 1) fused convert + stats: x -> (b1,b2), per-(b,c) sums ----------------
__global__ void convstats_kernel(const float* __restrict__ x) {
    int bc = blockIdx.x;                           // 0..1023
    const float4* p = (const float4*)(x + (size_t)bc * HWN);
    uint2* o1 = (uint2*)(d_b1 + (size_t)bc * HWN);
    uint2* o2 = (uint2*)(d_b2 + (size_t)bc * HWN);
    float s = 0.f, s2 = 0.f;
    for (int i = threadIdx.x; i < HWN/4; i += 256) {
        float4 v = p[i];
        float in[4] = {v.x, v.y, v.z, v.w};
        uint32_t hh[4], ll[4];
#pragma unroll
        for (int j = 0; j < 4; j++) {
            s  += in[j];
            s2 += in[j] * in[j];
            __nv_bfloat16 h = __float2bfloat16(in[j]);
            float hf = __bfloat162float(h);
            __nv_bfloat16 lo = __float2bfloat16(in[j] - hf);
            hh[j] = (uint32_t)__bfloat16_as_ushort(h);
            ll[j] = (uint32_t)__bfloat16_as_ushort(lo);
        }
        uint2 ph; ph.x = hh[0] | (hh[1] << 16); ph.y = hh[2] | (hh[3] << 16);
        uint2 pl; pl.x = ll[0] | (ll[1] << 16); pl.y = ll[2] | (ll[3] << 16);
        o1[i] = ph; o2[i] = pl;
    }
    for (int o = 16; o; o >>= 1) {
        s  += __shfl_down_sync(0xffffffffu, s, o);
        s2 += __shfl_down_sync(0xffffffffu, s2, o);
    }
    __shared__ float sh[8][2];
    int w = threadIdx.x >> 5, l = threadIdx.x & 31;
    if (l == 0) { sh[w][0] = s; sh[w][1] = s2; }
    __syncthreads();
    if (threadIdx.x == 0) {
        float S = 0.f, S2 = 0.f;
        for (int i = 0; i < 8; i++) { S += sh[i][0]; S2 += sh[i][1]; }
        d_Sx[bc] = S; d_Sxx[bc] = S2;
    }
}

// ---------------- 2) pack qkv rows + fold gn_bias ----------------
__global__ void pack_kernel(const float* __restrict__ qkvw,
                            const float* __restrict__ qkvb,
                            const float* __restrict__ gnb) {
    int rid = blockIdx.x * 128 + threadIdx.x;
    if (rid >= 768) return;
    int sel = rid / 256;
    int p   = rid % 256;
    int h = p >> 2, dd = p & 3;
    int src = h * 12 + sel * 4 + dd;
    const float* wrow = qkvw + src * 256;
    float* dst = (sel == 0 ? d_Wq : (sel == 1 ? d_Wk : d_Wv)) + p * 256;
    float dot = 0.f;
    for (int c = 0; c < 256; c++) {
        float w = wrow[c];
        dst[c] = w;
        dot += w * gnb[c];
    }
    float bt = qkvb[src] + dot;
    if (sel == 0) d_btq[p] = bt; else if (sel == 1) d_btk[p] = bt; else d_btv[p] = bt;
}

// ---------------- 3) group stats ----------------
__global__ void groupstats_kernel(const float* __restrict__ gnw) {
    int t = threadIdx.x;
    if (t >= 128) return;
    int b = t >> 5, g = t & 31;
    float s = 0.f, s2 = 0.f;
    for (int c8 = 0; c8 < 8; c8++) {
        int idx = b * 256 + g * 8 + c8;
        s += d_Sx[idx]; s2 += d_Sxx[idx];
    }
    const float n = 8.f * (float)HWN;
    float mean = s / n;
    float var  = (s2 - n * mean * mean) / (n - 1.f);
    float a = rsqrtf(var + 1e-5f);
    for (int c8 = 0; c8 < 8; c8++) {
        int c = g * 8 + c8;
        int idx = b * 256 + c;
        d_m[idx] = mean;
        d_a[idx] = a;
        float wa = gnw[c] * a;
        d_wa[idx] = wa;
        d_rp[idx] = wa * (d_Sx[idx] - (float)HWN * mean);
    }
}

// ---------------- 4) HMMA Gram: Gpart[b][split] = X_i X_j^T (bf16 2-way split) ----------------
// grid.x: 0->(0,0) 1->(0,1) 2->(1,1); (1,0) recovered by symmetry in reduceG.
__global__ void __launch_bounds__(256, 2) gram_mma_kernel() {
    extern __shared__ char sm[];
    int b = blockIdx.z, split = blockIdx.y, t = blockIdx.x;
    int i0 = (t == 2) ? 128 : 0;
    int j0 = (t == 0) ? 0 : 128;
    int tid = threadIdx.x, wid = tid >> 5, l = tid & 31;
    int wr = wid >> 2, wc = wid & 3;
    uint32_t sb = smem_u32(sm);

    float acc[4][4][4] = {};
    int frag_row = ((l >> 3) & 1) * 8 + (l & 7);
    int koff = (l >> 4) * 8;

    for (int ch = 0; ch < 16; ch++) {
        int k0 = split * 1024 + ch * 64;
        // load 4 tiles: buf0=A1(i0,b1) buf1=A2(i0,b2) buf2=B1(j0,b1) buf3=B2(j0,b2)
#pragma unroll
        for (int it = 0; it < 16; it++) {
            int s = tid + it * 256;
            int buf = s >> 10;
            int r = (s >> 3) & 127;
            int c = s & 7;
            const __nv_bfloat16* base = ((buf & 1) ? d_b2 : d_b1)
                + (size_t)b * CHW + (size_t)((buf < 2) ? i0 : j0) * HWN;
            uint4 v = *(const uint4*)(base + (size_t)r * HWN + k0 + c * 8);
            uint32_t off = (uint32_t)(r * 128 + c * 16);
            *(uint4*)(sm + buf * 16384 + SWA(off)) = v;
        }
        __syncthreads();
#pragma unroll
        for (int ks = 0; ks < 4; ks++) {
            int kb = (ks * 16 + koff) * 2;
            uint32_t a[4][4], bf[2][4], bf2[2][4];
#pragma unroll
            for (int g = 0; g < 2; g++) {
                uint32_t off = (uint32_t)((wc * 32 + g * 16 + frag_row) * 128 + kb);
                ldm_x4(bf[g],  sb + 2 * 16384 + SWA(off));
                ldm_x4(bf2[g], sb + 3 * 16384 + SWA(off));
            }
#pragma unroll
            for (int mt = 0; mt < 4; mt++) {
                uint32_t off = (uint32_t)((wr * 64 + mt * 16 + frag_row) * 128 + kb);
                ldm_x4(a[mt], sb + SWA(off));
            }
#pragma unroll
            for (int mt = 0; mt < 4; mt++)
#pragma unroll
                for (int nt = 0; nt < 4; nt++) {
                    int g = nt >> 1, p = nt & 1;
                    mma_bf16(acc[mt][nt], a[mt], bf[g][p],  bf[g][p + 2]);   // A1*B1
                    mma_bf16(acc[mt][nt], a[mt], bf2[g][p], bf2[g][p + 2]);  // A1*B2
                }
#pragma unroll
            for (int mt = 0; mt < 4; mt++) {
                uint32_t off = (uint32_t)((wr * 64 + mt * 16 + frag_row) * 128 + kb);
                ldm_x4(a[mt], sb + 16384 + SWA(off));
            }
#pragma unroll
            for (int mt = 0; mt < 4; mt++)
#pragma unroll
                for (int nt = 0; nt < 4; nt++) {
                    int g = nt >> 1, p = nt & 1;
                    mma_bf16(acc[mt][nt], a[mt], bf[g][p], bf[g][p + 2]);    // A2*B1
                }
        }
        __syncthreads();
    }
    float* gp = d_Gpart + ((size_t)(b * GSPLITS + split)) * 65536;
#pragma unroll
    for (int mt = 0; mt < 4; mt++)
#pragma unroll
        for (int nt = 0; nt < 4; nt++) {
            int row = i0 + wr * 64 + mt * 16 + (l >> 2);
            int col = j0 + wc * 32 + nt * 8 + (l & 3) * 2;
            float2 v0; v0.x = acc[mt][nt][0]; v0.y = acc[mt][nt][1];
            float2 v1; v1.x = acc[mt][nt][2]; v1.y = acc[mt][nt][3];
            *(float2*)&gp[row * 256 + col] = v0;
            *(float2*)&gp[(row + 8) * 256 + col] = v1;
        }
}

// ---------------- 5) reduce partials (with symmetry) + GN corrections -> G' ----------------
__global__ void reduceG_kernel() {
    int e = blockIdx.x * 256 + threadIdx.x;
    int b = e >> 16;
    int ij = e & 65535;
    int i = ij >> 8, j = ij & 255;
    int rij = (i >= 128 && j < 128) ? (j * 256 + i) : ij;
    size_t base = (size_t)b * GSPLITS * 65536 + rij;
    float sum = 0.f;
    for (int s = 0; s < GSPLITS; s++) sum += d_Gpart[base + (size_t)s * 65536];
    int bi = b * 256 + i, bj = b * 256 + j;
    float g = d_wa[bi] * d_wa[bj] *
              (sum - d_m[bi] * d_Sx[bj] - d_m[bj] * d_Sx[bi] + (float)HWN * d_m[bi] * d_m[bj]);
    d_G[e] = g;
}

// ---------------- small fp32 GEMMs (M=N=K=256) ----------------
// MODE 0: U = Wq @ G' ; MODE 1: E = out_w @ T
template<int MODE>
__global__ void gemm64(const float* __restrict__ Aext) {
    int b = blockIdx.z;
    const float* A = (MODE == 0) ? d_Wq : Aext;
    const float* B = ((MODE == 0) ? d_G : d_T) + b * 65536;
    float* Cp = ((MODE == 0) ? d_U : d_E) + b * 65536;

    __shared__ float As[16][64];
    __shared__ float Bs[16][64];
    int m0 = blockIdx.x * 64, n0 = blockIdx.y * 64;
    int tid = threadIdx.x;
    int tx = tid & 15, ty = tid >> 4;
    int ar = tid >> 2, asg = tid & 3;
    int br = tid >> 4, bc = tid & 15;
    float acc[4][4] = {};
    for (int k0 = 0; k0 < 256; k0 += 16) {
        float4 av = *(const float4*)&A[(m0 + ar) * 256 + k0 + asg * 4];
        As[asg*4+0][ar] = av.x; As[asg*4+1][ar] = av.y; As[asg*4+2][ar] = av.z; As[asg*4+3][ar] = av.w;
        float4 bv = *(const float4*)&B[(k0 + br) * 256 + n0 + bc * 4];
        *(float4*)&Bs[br][bc * 4] = bv;
        __syncthreads();
#pragma unroll
        for (int kk = 0; kk < 16; kk++) {
            float4 a4 = *(const float4*)&As[kk][ty * 4];
            float4 b4 = *(const float4*)&Bs[kk][tx * 4];
            float avv[4] = {a4.x, a4.y, a4.z, a4.w};
            float bvv[4] = {b4.x, b4.y, b4.z, b4.w};
#pragma unroll
            for (int i = 0; i < 4; i++)
#pragma unroll
                for (int j = 0; j < 4; j++)
                    acc[i][j] += avv[i] * bvv[j];
        }
        __syncthreads();
    }
#pragma unroll
    for (int i = 0; i < 4; i++) {
        int m = m0 + ty * 4 + i;
        float4 v; v.x = acc[i][0]; v.y = acc[i][1]; v.z = acc[i][2]; v.w = acc[i][3];
        *(float4*)&Cp[m * 256 + n0 + tx * 4] = v;
    }
}

// ---------------- 6) p-vectors ----------------
__global__ void pvec_kernel() {
    int rid = blockIdx.x * 128 + threadIdx.x;
    if (rid >= 2048) return;
    int b = rid / 512;
    int q = rid % 512;
    int sel = q / 256, p = q % 256;
    const float* w = (sel ? d_Wk : d_Wq) + p * 256;
    const float* r = d_rp + b * 256;
    float s = 0.f;
    for (int c = 0; c < 256; c++) s += w[c] * r[c];
    (sel ? d_pk : d_pq)[b * 256 + p] = s;
}

// ---------------- 7) raw scores ----------------
__global__ void scores_kernel() {
    int bi = blockIdx.x;
    int b = bi >> 6, h = bi & 63;
    int tid = threadIdx.x;
    int pair = tid >> 4, l = tid & 15;
    int dd = pair >> 2, ee = pair & 3;
    int pU = h * 4 + dd, pK = h * 4 + ee;
    const float* u  = d_U + (size_t)b * 65536 + pU * 256;
    const float* wk = d_Wk + pK * 256;
    float s = 0.f;
    for (int c = l; c < 256; c += 16) s += u[c] * wk[c];
    for (int o = 8; o; o >>= 1) s += __shfl_down_sync(0xffffffffu, s, o, 16);
    if (l == 0) {
        s += d_pq[b * 256 + pU] * d_btk[pK]
           + d_btq[pU] * d_pk[b * 256 + pK]
           + (float)HWN * d_btq[pU] * d_btk[pK];
        d_sc[(b * 64 + h) * 16 + pair] = 0.5f * s;
    }
}

// ---------------- 8) softmax over heads axis ----------------
__global__ void softmax_kernel() {
    int b = blockIdx.x;
    int w = threadIdx.x >> 5;
    int l = threadIdx.x & 31;
    float v0 = d_sc[((b * 64 + l) << 4) + w];
    float v1 = d_sc[((b * 64 + l + 32) << 4) + w];
    float mx = fmaxf(v0, v1);
    for (int o = 16; o; o >>= 1) mx = fmaxf(mx, __shfl_xor_sync(0xffffffffu, mx, o));
    float e0 = expf(v0 - mx), e1 = expf(v1 - mx);
    float s = e0 + e1;
    for (int o = 16; o; o >>= 1) s += __shfl_xor_sync(0xffffffffu, s, o);
    d_Smx[((b * 64 + l) << 4) + w] = e0 / s;
    d_Smx[((b * 64 + l + 32) << 4) + w] = e1 / s;
}

// ---------------- 9) T = BlockDiag(S) Wv diag(gnw) ----------------
__global__ void t_kernel(const float* __restrict__ gnw) {
    int bi = blockIdx.x;
    int b = bi >> 6, h = bi & 63;
    int c = threadIdx.x;
    __shared__ float Ssh[16];
    if (c < 16) Ssh[c] = d_Smx[(b * 64 + h) * 16 + c];
    __syncthreads();
    float w0 = d_Wv[(h*4+0)*256 + c];
    float w1 = d_Wv[(h*4+1)*256 + c];
    float w2 = d_Wv[(h*4+2)*256 + c];
    float w3 = d_Wv[(h*4+3)*256 + c];
    float gc = gnw[c];
#pragma unroll
    for (int dd = 0; dd < 4; dd++) {
        float s = Ssh[dd*4+0]*w0 + Ssh[dd*4+1]*w1 + Ssh[dd*4+2]*w2 + Ssh[dd*4+3]*w3;
        d_T[((size_t)b * 256 + h * 4 + dd) * 256 + c] = gc * s;
    }
    if (c < 4) {
        float tv = 0.f;
        for (int e = 0; e < 4; e++) tv += Ssh[c * 4 + e] * d_btv[h * 4 + e];
        d_tv[b * 256 + h * 4 + c] = tv;
    }
}

// ---------------- 10) fold: F = E diag(a) -> bf16 split; g = out_b + out_w tv - F m ----------------
__global__ void fold_kernel(const float* __restrict__ outw,
                            const float* __restrict__ outb) {
    int b = blockIdx.x;
    int o = threadIdx.x;
    const float* ow = outw + o * 256;
    float e = outb[o];
    for (int p = 0; p < 256; p++) e += ow[p] * d_tv[b * 256 + p];
    float gacc = 0.f;
    for (int c = 0; c < 256; c++) {
        int idx = (b * 256 + o) * 256 + c;
        float f = d_E[idx] * d_a[b * 256 + c];
        __nv_bfloat16 h = __float2bfloat16(f);
        d_F1[idx] = h;
        d_F2[idx] = __float2bfloat16(f - __bfloat162float(h));
        gacc += f * d_m[b * 256 + c];
    }
    d_g[b * 256 + o] = e - gacc;
}

// ---------------- 11) HMMA final GEMM: out = F@x + g + skip ----------------
__global__ void __launch_bounds__(256, 2) fgemm_kernel(const float* __restrict__ x,
                                                       float* __restrict__ out) {
    extern __shared__ char sm[];
    int b = blockIdx.z;
    int m0 = blockIdx.x * 128;
    int n0 = blockIdx.y * 128;
    int tid = threadIdx.x, wid = tid >> 5, l = tid & 31;
    int wr = wid >> 2, wc = wid & 3;
    uint32_t sb = smem_u32(sm);

    const __nv_bfloat16* A1 = d_F1 + b * 65536;
    const __nv_bfloat16* A2 = d_F2 + b * 65536;
    const __nv_bfloat16* B1 = d_b1 + (size_t)b * CHW;
    const __nv_bfloat16* B2 = d_b2 + (size_t)b * CHW;

    float acc[4][4][4] = {};
    int frag_row = ((l >> 3) & 1) * 8 + (l & 7);
    int koff = (l >> 4) * 8;

    for (int ch = 0; ch < 4; ch++) {
        int k0 = ch * 64;
#pragma unroll
        for (int it = 0; it < 16; it++) {
            int s = tid + it * 256;
            int buf = s >> 10;
            if (buf < 2) {
                int r = (s >> 3) & 127;
                int c = s & 7;
                const __nv_bfloat16* src = buf ? A2 : A1;
                uint4 v = *(const uint4*)(src + (m0 + r) * 256 + k0 + c * 8);
                uint32_t off = (uint32_t)(r * 128 + c * 16);
                *(uint4*)(sm + buf * 16384 + SWA(off)) = v;
            } else {
                int v2 = s & 1023;
                int kr = v2 >> 4;      // 0..63
                int c = v2 & 15;       // 16B chunk of 256B row
                const __nv_bfloat16* src = (buf == 2) ? B1 : B2;
                uint4 v = *(const uint4*)(src + (size_t)(k0 + kr) * HWN + n0 + c * 8);
                uint32_t off = (uint32_t)(kr * 256 + c * 16);
                *(uint4*)(sm + buf * 16384 + SWB(off)) = v;
            }
        }
        __syncthreads();
#pragma unroll
        for (int ks = 0; ks < 4; ks++) {
            int kb = (ks * 16 + koff) * 2;               // A k-byte offset
            uint32_t a[4][4], bf[2][4], bf2[2][4];
            // B via trans: addr row = k (frag_row on k), col offset = koff on n
#pragma unroll
            for (int g = 0; g < 2; g++) {
                uint32_t off = (uint32_t)((ks * 16 + frag_row) * 256
                                          + (wc * 32 + g * 16 + koff) * 2);
                ldm_x4_t(bf[g],  sb + 2 * 16384 + SWB(off));
                ldm_x4_t(bf2[g], sb + 3 * 16384 + SWB(off));
            }
#pragma unroll
            for (int mt = 0; mt < 4; mt++) {
                uint32_t off = (uint32_t)((wr * 64 + mt * 16 + frag_row) * 128 + kb);
                ldm_x4(a[mt], sb + SWA(off));
            }
#pragma unroll
            for (int mt = 0; mt < 4; mt++)
#pragma unroll
                for (int nt = 0; nt < 4; nt++) {
                    int g = nt >> 1, p = nt & 1;
                    mma_bf16(acc[mt][nt], a[mt], bf[g][p*2],  bf[g][p*2+1]);   // F1*b1
                    mma_bf16(acc[mt][nt], a[mt], bf2[g][p*2], bf2[g][p*2+1]);  // F1*b2
                }
#pragma unroll
            for (int mt = 0; mt < 4; mt++) {
                uint32_t off = (uint32_t)((wr * 64 + mt * 16 + frag_row) * 128 + kb);
                ldm_x4(a[mt], sb + 16384 + SWA(off));
            }
#pragma unroll
            for (int mt = 0; mt < 4; mt++)
#pragma unroll
                for (int nt = 0; nt < 4; nt++) {
                    int g = nt >> 1, p = nt & 1;
                    mma_bf16(acc[mt][nt], a[mt], bf[g][p*2], bf[g][p*2+1]);    // F2*b1
                }
        }
        __syncthreads();
    }
    // epilogue: + g[m] + x[m][n]
    const float* xb = x + (size_t)b * CHW;
    float* ob = out + (size_t)b * CHW;
#pragma unroll
    for (int mt = 0; mt < 4; mt++) {
        int row = m0 + wr * 64 + mt * 16 + (l >> 2);
        float g0 = d_g[b * 256 + row];
        float g1 = d_g[b * 256 + row + 8];
#pragma unroll
        for (int nt = 0; nt < 4; nt++) {
            int col = n0 + wc * 32 + nt * 8 + (l & 3) * 2;
            float2 s0 = *(const float2*)&xb[(size_t)row * HWN + col];
            float2 s1 = *(const float2*)&xb[(size_t)(row + 8) * HWN + col];
            float2 v0, v1;
            v0.x = acc[mt][nt][0] + g0 + s0.x;
            v0.y = acc[mt][nt][1] + g0 + s0.y;
            v1.x = acc[mt][nt][2] + g1 + s1.x;
            v1.y = acc[mt][nt][3] + g1 + s1.y;
            *(float2*)&ob[(size_t)row * HWN + col] = v0;
            *(float2*)&ob[(size_t)(row + 8) * HWN + col] = v1;
        }
    }
}

// ---------------- launch ----------------
extern "C" void kernel_launch(void* const* d_in, const int* in_sizes, int n_in,
                              void* d_out, int out_size) {
    const float* x    = (const float*)d_in[0];
    const float* gnw  = (const float*)d_in[1];
    const float* gnb  = (const float*)d_in[2];
    const float* qkvw = (const float*)d_in[3];
    const float* qkvb = (const float*)d_in[4];
    const float* outw = (const float*)d_in[5];
    const float* outb = (const float*)d_in[6];
    float* out = (float*)d_out;

    cudaFuncSetAttribute(gram_mma_kernel, cudaFuncAttributeMaxDynamicSharedMemorySize, 65536);
    cudaFuncSetAttribute(fgemm_kernel,    cudaFuncAttributeMaxDynamicSharedMemorySize, 65536);

    convstats_kernel<<<BATCH * CC, 256>>>(x);
    pack_kernel<<<6, 128>>>(qkvw, qkvb, gnb);
    groupstats_kernel<<<1, 128>>>(gnw);
    gram_mma_kernel<<<dim3(3, GSPLITS, BATCH), 256, 65536>>>();
    reduceG_kernel<<<1024, 256>>>();
    gemm64<0><<<dim3(4, 4, BATCH), 256>>>(nullptr);
    pvec_kernel<<<16, 128>>>();
    scores_kernel<<<BATCH * 64, 256>>>();
    softmax_kernel<<<BATCH, 512>>>();
    t_kernel<<<BATCH * 64, 256>>>(gnw);
    gemm64<1><<<dim3(4, 4, BATCH), 256>>>(outw);
    fold_kernel<<<BATCH, 256>>>(outw, outb);
    fgemm_kernel<<<dim3(2, HWN / 128, BATCH), 256, 65536>>>(x, out);
}

// round 8
// speedup vs baseline: 2.2022x; 1.1117x over previous
#include <cuda_runtime.h>
#include <cuda_bf16.h>
#include <math.h>
#include <stdint.h>

#define HWN   16384
#define CC    256
#define BATCH 4
#define CHW   (CC*HWN)
#define GSPLITS 12
#define GCHUNKS 256          // total K-chunks of 64 across HWN

// ---------------- scratch (static __device__, no allocations) ----------------
__device__ __align__(16) float d_Sx[BATCH*CC];
__device__ __align__(16) float d_Sxx[BATCH*CC];
__device__ __align__(16) float d_m[BATCH*CC];
__device__ __align__(16) float d_a[BATCH*CC];
__device__ __align__(16) float d_wa[BATCH*CC];
__device__ __align__(16) float d_rp[BATCH*CC];
__device__ __align__(16) float d_Wq[CC*CC];
__device__ __align__(16) float d_Wk[CC*CC];
__device__ __align__(16) float d_Wv[CC*CC];
__device__ __align__(16) float d_btq[CC];
__device__ __align__(16) float d_btk[CC];
__device__ __align__(16) float d_btv[CC];
__device__ __align__(16) __nv_bfloat16 d_b1[BATCH*CHW];        // 32 MB
__device__ __align__(16) __nv_bfloat16 d_b2[BATCH*CHW];        // 32 MB
__device__ __align__(16) float d_Gpart[BATCH*GSPLITS*CC*CC];
__device__ __align__(16) float d_G[BATCH*CC*CC];
__device__ __align__(16) float d_U[BATCH*CC*CC];
__device__ __align__(16) float d_pq[BATCH*CC];
__device__ __align__(16) float d_pk[BATCH*CC];
__device__ __align__(16) float d_sc[BATCH*64*16];
__device__ __align__(16) float d_Smx[BATCH*64*16];
__device__ __align__(16) float d_T[BATCH*CC*CC];
__device__ __align__(16) float d_tv[BATCH*CC];
__device__ __align__(16) float d_E[BATCH*CC*CC];
__device__ __align__(16) __nv_bfloat16 d_F1[BATCH*CC*CC];
__device__ __align__(16) __nv_bfloat16 d_F2[BATCH*CC*CC];
__device__ __align__(16) float d_g[BATCH*CC];

// ---------------- mma / ldmatrix / cp.async helpers (baseline PTX, sm_80+) ----------------
__device__ __forceinline__ uint32_t smem_u32(const void* p) {
    uint32_t a;
    asm("{ .reg .u64 t; cvta.to.shared.u64 t, %1; cvt.u32.u64 %0, t; }" : "=r"(a) : "l"(p));
    return a;
}
__device__ __forceinline__ void ldm_x4(uint32_t* r, uint32_t addr) {
    asm volatile("ldmatrix.sync.aligned.m8n8.x4.shared.b16 {%0,%1,%2,%3}, [%4];"
                 : "=r"(r[0]), "=r"(r[1]), "=r"(r[2]), "=r"(r[3]) : "r"(addr));
}
__device__ __forceinline__ void ldm_x4_t(uint32_t* r, uint32_t addr) {
    asm volatile("ldmatrix.sync.aligned.m8n8.x4.trans.shared.b16 {%0,%1,%2,%3}, [%4];"
                 : "=r"(r[0]), "=r"(r[1]), "=r"(r[2]), "=r"(r[3]) : "r"(addr));
}
__device__ __forceinline__ void mma_bf16(float* c, const uint32_t* a,
                                         uint32_t b0, uint32_t b1) {
    asm volatile("mma.sync.aligned.m16n8k16.row.col.f32.bf16.bf16.f32 "
                 "{%0,%1,%2,%3}, {%4,%5,%6,%7}, {%8,%9}, {%0,%1,%2,%3};"
                 : "+f"(c[0]), "+f"(c[1]), "+f"(c[2]), "+f"(c[3])
                 : "r"(a[0]), "r"(a[1]), "r"(a[2]), "r"(a[3]), "r"(b0), "r"(b1));
}
__device__ __forceinline__ void cp16(uint32_t dst, const void* src) {
    asm volatile("cp.async.cg.shared.global [%0], [%1], 16;" :: "r"(dst), "l"(src) : "memory");
}
#define CP_COMMIT()  asm volatile("cp.async.commit_group;" ::: "memory")
#define CP_WAIT_1()  asm volatile("cp.async.wait_group 1;" ::: "memory")
#define CP_WAIT_0()  asm volatile("cp.async.wait_group 0;" ::: "memory")

// SW for 128B-row tiles: XOR 16B-chunk idx (bits 4-6) with row%8 (bits 7-9)
#define SWA(o) ((o) ^ (((o) >> 3) & 0x70))
// SW for 256B-row tiles: XOR bits 4-6 with k-row%8 (bits 8-10)
#define SWB(o) ((o) ^ ((((o) >> 8) & 7) << 4))

// ---------------- 1) fused convert + stats ----------------
__global__ void convstats_kernel(const float* __restrict__ x) {
    int bc = blockIdx.x;
    const float4* p = (const float4*)(x + (size_t)bc * HWN);
    uint2* o1 = (uint2*)(d_b1 + (size_t)bc * HWN);
    uint2* o2 = (uint2*)(d_b2 + (size_t)bc * HWN);
    float s = 0.f, s2 = 0.f;
    for (int i = threadIdx.x; i < HWN/4; i += 256) {
        float4 v = p[i];
        float in[4] = {v.x, v.y, v.z, v.w};
        uint32_t hh[4], ll[4];
#pragma unroll
        for (int j = 0; j < 4; j++) {
            s  += in[j];
            s2 += in[j] * in[j];
            __nv_bfloat16 h = __float2bfloat16(in[j]);
            float hf = __bfloat162float(h);
            __nv_bfloat16 lo = __float2bfloat16(in[j] - hf);
            hh[j] = (uint32_t)__bfloat16_as_ushort(h);
            ll[j] = (uint32_t)__bfloat16_as_ushort(lo);
        }
        uint2 ph; ph.x = hh[0] | (hh[1] << 16); ph.y = hh[2] | (hh[3] << 16);
        uint2 pl; pl.x = ll[0] | (ll[1] << 16); pl.y = ll[2] | (ll[3] << 16);
        o1[i] = ph; o2[i] = pl;
    }
    for (int o = 16; o; o >>= 1) {
        s  += __shfl_down_sync(0xffffffffu, s, o);
        s2 += __shfl_down_sync(0xffffffffu, s2, o);
    }
    __shared__ float sh[8][2];
    int w = threadIdx.x >> 5, l = threadIdx.x & 31;
    if (l == 0) { sh[w][0] = s; sh[w][1] = s2; }
    __syncthreads();
    if (threadIdx.x == 0) {
        float S = 0.f, S2 = 0.f;
        for (int i = 0; i < 8; i++) { S += sh[i][0]; S2 += sh[i][1]; }
        d_Sx[bc] = S; d_Sxx[bc] = S2;
    }
}

// ---------------- 2) pack qkv rows + fold gn_bias ----------------
__global__ void pack_kernel(const float* __restrict__ qkvw,
                            const float* __restrict__ qkvb,
                            const float* __restrict__ gnb) {
    int rid = blockIdx.x * 128 + threadIdx.x;
    if (rid >= 768) return;
    int sel = rid / 256;
    int p   = rid % 256;
    int h = p >> 2, dd = p & 3;
    int src = h * 12 + sel * 4 + dd;
    const float* wrow = qkvw + src * 256;
    float* dst = (sel == 0 ? d_Wq : (sel == 1 ? d_Wk : d_Wv)) + p * 256;
    float dot = 0.f;
    for (int c = 0; c < 256; c++) {
        float w = wrow[c];
        dst[c] = w;
        dot += w * gnb[c];
    }
    float bt = qkvb[src] + dot;
    if (sel == 0) d_btq[p] = bt; else if (sel == 1) d_btk[p] = bt; else d_btv[p] = bt;
}

// ---------------- 3) group stats ----------------
__global__ void groupstats_kernel(const float* __restrict__ gnw) {
    int t = threadIdx.x;
    if (t >= 128) return;
    int b = t >> 5, g = t & 31;
    float s = 0.f, s2 = 0.f;
    for (int c8 = 0; c8 < 8; c8++) {
        int idx = b * 256 + g * 8 + c8;
        s += d_Sx[idx]; s2 += d_Sxx[idx];
    }
    const float n = 8.f * (float)HWN;
    float mean = s / n;
    float var  = (s2 - n * mean * mean) / (n - 1.f);
    float a = rsqrtf(var + 1e-5f);
    for (int c8 = 0; c8 < 8; c8++) {
        int c = g * 8 + c8;
        int idx = b * 256 + c;
        d_m[idx] = mean;
        d_a[idx] = a;
        float wa = gnw[c] * a;
        d_wa[idx] = wa;
        d_rp[idx] = wa * (d_Sx[idx] - (float)HWN * mean);
    }
}

// ---------------- 4) HMMA Gram, 2-stage cp.async pipeline ----------------
// grid.x: 0->(0,0) 1->(0,1) 2->(1,1); (1,0) by symmetry in reduceG.
// GSPLITS=12 non-uniform: splits 0-3 get 22 chunks, 4-11 get 21 (total 256).
__global__ void __launch_bounds__(256, 1) gram_mma_kernel() {
    extern __shared__ char sm[];
    int b = blockIdx.z, split = blockIdx.y, t = blockIdx.x;
    int i0 = (t == 2) ? 128 : 0;
    int j0 = (t == 0) ? 0 : 128;
    int nch = 21 + (split < 4 ? 1 : 0);
    int ch0 = split * 21 + (split < 4 ? split : 4);
    int tid = threadIdx.x, wid = tid >> 5, l = tid & 31;
    int wr = wid >> 2, wc = wid & 3;
    uint32_t sb = smem_u32(sm);

    float acc[4][4][4] = {};
    int frag_row = ((l >> 3) & 1) * 8 + (l & 7);
    int koff = (l >> 4) * 8;

    // precompute per-thread load geometry (same for all 16 iterations pattern)
    // issue one chunk into a stage
    auto issue = [&](int ch, int st) {
        int k0 = (ch0 + ch) * 64;
#pragma unroll
        for (int it = 0; it < 16; it++) {
            int s = tid + it * 256;
            int buf = s >> 10;
            int r = (s >> 3) & 127;
            int c = s & 7;
            const __nv_bfloat16* base = ((buf & 1) ? d_b2 : d_b1)
                + (size_t)b * CHW + (size_t)((buf < 2) ? i0 : j0) * HWN;
            uint32_t dst = sb + st * 65536 + buf * 16384
                         + SWA((uint32_t)(r * 128 + c * 16));
            cp16(dst, base + (size_t)r * HWN + k0 + c * 8);
        }
        CP_COMMIT();
    };

    issue(0, 0);
    for (int ch = 0; ch < nch; ch++) {
        int st = ch & 1;
        if (ch + 1 < nch) { issue(ch + 1, st ^ 1); CP_WAIT_1(); }
        else              { CP_WAIT_0(); }
        __syncthreads();
        uint32_t stb = sb + st * 65536;
#pragma unroll
        for (int ks = 0; ks < 4; ks++) {
            int kb = (ks * 16 + koff) * 2;
            uint32_t a[4][4], bf[2][4], bf2[2][4];
#pragma unroll
            for (int g = 0; g < 2; g++) {
                uint32_t off = (uint32_t)((wc * 32 + g * 16 + frag_row) * 128 + kb);
                ldm_x4(bf[g],  stb + 2 * 16384 + SWA(off));
                ldm_x4(bf2[g], stb + 3 * 16384 + SWA(off));
            }
#pragma unroll
            for (int mt = 0; mt < 4; mt++) {
                uint32_t off = (uint32_t)((wr * 64 + mt * 16 + frag_row) * 128 + kb);
                ldm_x4(a[mt], stb + SWA(off));
            }
#pragma unroll
            for (int mt = 0; mt < 4; mt++)
#pragma unroll
                for (int nt = 0; nt < 4; nt++) {
                    int g = nt >> 1, p = nt & 1;
                    mma_bf16(acc[mt][nt], a[mt], bf[g][p],  bf[g][p + 2]);   // A1*B1
                    mma_bf16(acc[mt][nt], a[mt], bf2[g][p], bf2[g][p + 2]);  // A1*B2
                }
#pragma unroll
            for (int mt = 0; mt < 4; mt++) {
                uint32_t off = (uint32_t)((wr * 64 + mt * 16 + frag_row) * 128 + kb);
                ldm_x4(a[mt], stb + 16384 + SWA(off));
            }
#pragma unroll
            for (int mt = 0; mt < 4; mt++)
#pragma unroll
                for (int nt = 0; nt < 4; nt++) {
                    int g = nt >> 1, p = nt & 1;
                    mma_bf16(acc[mt][nt], a[mt], bf[g][p], bf[g][p + 2]);    // A2*B1
                }
        }
        __syncthreads();
    }
    float* gp = d_Gpart + ((size_t)(b * GSPLITS + split)) * 65536;
#pragma unroll
    for (int mt = 0; mt < 4; mt++)
#pragma unroll
        for (int nt = 0; nt < 4; nt++) {
            int row = i0 + wr * 64 + mt * 16 + (l >> 2);
            int col = j0 + wc * 32 + nt * 8 + (l & 3) * 2;
            float2 v0; v0.x = acc[mt][nt][0]; v0.y = acc[mt][nt][1];
            float2 v1; v1.x = acc[mt][nt][2]; v1.y = acc[mt][nt][3];
            *(float2*)&gp[row * 256 + col] = v0;
            *(float2*)&gp[(row + 8) * 256 + col] = v1;
        }
}

// ---------------- 5) reduce partials (symmetry) + GN corrections -> G' ----------------
__global__ void reduceG_kernel() {
    int e = blockIdx.x * 256 + threadIdx.x;
    int b = e >> 16;
    int ij = e & 65535;
    int i = ij >> 8, j = ij & 255;
    int rij = (i >= 128 && j < 128) ? (j * 256 + i) : ij;
    size_t base = (size_t)b * GSPLITS * 65536 + rij;
    float sum = 0.f;
    for (int s = 0; s < GSPLITS; s++) sum += d_Gpart[base + (size_t)s * 65536];
    int bi = b * 256 + i, bj = b * 256 + j;
    float g = d_wa[bi] * d_wa[bj] *
              (sum - d_m[bi] * d_Sx[bj] - d_m[bj] * d_Sx[bi] + (float)HWN * d_m[bi] * d_m[bj]);
    d_G[e] = g;
}

// ---------------- small fp32 GEMMs (M=N=K=256) ----------------
template<int MODE>
__global__ void gemm64(const float* __restrict__ Aext) {
    int b = blockIdx.z;
    const float* A = (MODE == 0) ? d_Wq : Aext;
    const float* B = ((MODE == 0) ? d_G : d_T) + b * 65536;
    float* Cp = ((MODE == 0) ? d_U : d_E) + b * 65536;

    __shared__ float As[16][64];
    __shared__ float Bs[16][64];
    int m0 = blockIdx.x * 64, n0 = blockIdx.y * 64;
    int tid = threadIdx.x;
    int tx = tid & 15, ty = tid >> 4;
    int ar = tid >> 2, asg = tid & 3;
    int br = tid >> 4, bc = tid & 15;
    float acc[4][4] = {};
    for (int k0 = 0; k0 < 256; k0 += 16) {
        float4 av = *(const float4*)&A[(m0 + ar) * 256 + k0 + asg * 4];
        As[asg*4+0][ar] = av.x; As[asg*4+1][ar] = av.y; As[asg*4+2][ar] = av.z; As[asg*4+3][ar] = av.w;
        float4 bv = *(const float4*)&B[(k0 + br) * 256 + n0 + bc * 4];
        *(float4*)&Bs[br][bc * 4] = bv;
        __syncthreads();
#pragma unroll
        for (int kk = 0; kk < 16; kk++) {
            float4 a4 = *(const float4*)&As[kk][ty * 4];
            float4 b4 = *(const float4*)&Bs[kk][tx * 4];
            float avv[4] = {a4.x, a4.y, a4.z, a4.w};
            float bvv[4] = {b4.x, b4.y, b4.z, b4.w};
#pragma unroll
            for (int i = 0; i < 4; i++)
#pragma unroll
                for (int j = 0; j < 4; j++)
                    acc[i][j] += avv[i] * bvv[j];
        }
        __syncthreads();
    }
#pragma unroll
    for (int i = 0; i < 4; i++) {
        int m = m0 + ty * 4 + i;
        float4 v; v.x = acc[i][0]; v.y = acc[i][1]; v.z = acc[i][2]; v.w = acc[i][3];
        *(float4*)&Cp[m * 256 + n0 + tx * 4] = v;
    }
}

// ---------------- 6) p-vectors ----------------
__global__ void pvec_kernel() {
    int rid = blockIdx.x * 128 + threadIdx.x;
    if (rid >= 2048) return;
    int b = rid / 512;
    int q = rid % 512;
    int sel = q / 256, p = q % 256;
    const float* w = (sel ? d_Wk : d_Wq) + p * 256;
    const float* r = d_rp + b * 256;
    float s = 0.f;
    for (int c = 0; c < 256; c++) s += w[c] * r[c];
    (sel ? d_pk : d_pq)[b * 256 + p] = s;
}

// ---------------- 7) raw scores ----------------
__global__ void scores_kernel() {
    int bi = blockIdx.x;
    int b = bi >> 6, h = bi & 63;
    int tid = threadIdx.x;
    int pair = tid >> 4, l = tid & 15;
    int dd = pair >> 2, ee = pair & 3;
    int pU = h * 4 + dd, pK = h * 4 + ee;
    const float* u  = d_U + (size_t)b * 65536 + pU * 256;
    const float* wk = d_Wk + pK * 256;
    float s = 0.f;
    for (int c = l; c < 256; c += 16) s += u[c] * wk[c];
    for (int o = 8; o; o >>= 1) s += __shfl_down_sync(0xffffffffu, s, o, 16);
    if (l == 0) {
        s += d_pq[b * 256 + pU] * d_btk[pK]
           + d_btq[pU] * d_pk[b * 256 + pK]
           + (float)HWN * d_btq[pU] * d_btk[pK];
        d_sc[(b * 64 + h) * 16 + pair] = 0.5f * s;
    }
}

// ---------------- 8) softmax over heads axis ----------------
__global__ void softmax_kernel() {
    int b = blockIdx.x;
    int w = threadIdx.x >> 5;
    int l = threadIdx.x & 31;
    float v0 = d_sc[((b * 64 + l) << 4) + w];
    float v1 = d_sc[((b * 64 + l + 32) << 4) + w];
    float mx = fmaxf(v0, v1);
    for (int o = 16; o; o >>= 1) mx = fmaxf(mx, __shfl_xor_sync(0xffffffffu, mx, o));
    float e0 = expf(v0 - mx), e1 = expf(v1 - mx);
    float s = e0 + e1;
    for (int o = 16; o; o >>= 1) s += __shfl_xor_sync(0xffffffffu, s, o);
    d_Smx[((b * 64 + l) << 4) + w] = e0 / s;
    d_Smx[((b * 64 + l + 32) << 4) + w] = e1 / s;
}

// ---------------- 9) T = BlockDiag(S) Wv diag(gnw) ----------------
__global__ void t_kernel(const float* __restrict__ gnw) {
    int bi = blockIdx.x;
    int b = bi >> 6, h = bi & 63;
    int c = threadIdx.x;
    __shared__ float Ssh[16];
    if (c < 16) Ssh[c] = d_Smx[(b * 64 + h) * 16 + c];
    __syncthreads();
    float w0 = d_Wv[(h*4+0)*256 + c];
    float w1 = d_Wv[(h*4+1)*256 + c];
    float w2 = d_Wv[(h*4+2)*256 + c];
    float w3 = d_Wv[(h*4+3)*256 + c];
    float gc = gnw[c];
#pragma unroll
    for (int dd = 0; dd < 4; dd++) {
        float s = Ssh[dd*4+0]*w0 + Ssh[dd*4+1]*w1 + Ssh[dd*4+2]*w2 + Ssh[dd*4+3]*w3;
        d_T[((size_t)b * 256 + h * 4 + dd) * 256 + c] = gc * s;
    }
    if (c < 4) {
        float tv = 0.f;
        for (int e = 0; e < 4; e++) tv += Ssh[c * 4 + e] * d_btv[h * 4 + e];
        d_tv[b * 256 + h * 4 + c] = tv;
    }
}

// ---------------- 10) fold: F = E diag(a) -> bf16 split ----------------
__global__ void fold_kernel(const float* __restrict__ outw,
                            const float* __restrict__ outb) {
    int b = blockIdx.x;
    int o = threadIdx.x;
    const float* ow = outw + o * 256;
    float e = outb[o];
    for (int p = 0; p < 256; p++) e += ow[p] * d_tv[b * 256 + p];
    float gacc = 0.f;
    for (int c = 0; c < 256; c++) {
        int idx = (b * 256 + o) * 256 + c;
        float f = d_E[idx] * d_a[b * 256 + c];
        __nv_bfloat16 h = __float2bfloat16(f);
        d_F1[idx] = h;
        d_F2[idx] = __float2bfloat16(f - __bfloat162float(h));
        gacc += f * d_m[b * 256 + c];
    }
    d_g[b * 256 + o] = e - gacc;
}

// ---------------- 11) HMMA final GEMM, 2-stage cp.async: out = F@x + g + skip ----------------
__global__ void __launch_bounds__(256, 1) fgemm_kernel(const float* __restrict__ x,
                                                       float* __restrict__ out) {
    extern __shared__ char sm[];
    int b = blockIdx.z;
    int m0 = blockIdx.x * 128;
    int n0 = blockIdx.y * 128;
    int tid = threadIdx.x, wid = tid >> 5, l = tid & 31;
    int wr = wid >> 2, wc = wid & 3;
    uint32_t sb = smem_u32(sm);

    const __nv_bfloat16* A1 = d_F1 + b * 65536;
    const __nv_bfloat16* A2 = d_F2 + b * 65536;
    const __nv_bfloat16* B1 = d_b1 + (size_t)b * CHW;
    const __nv_bfloat16* B2 = d_b2 + (size_t)b * CHW;

    float acc[4][4][4] = {};
    int frag_row = ((l >> 3) & 1) * 8 + (l & 7);
    int koff = (l >> 4) * 8;

    auto issue = [&](int ch, int st) {
        int k0 = ch * 64;
#pragma unroll
        for (int it = 0; it < 16; it++) {
            int s = tid + it * 256;
            int buf = s >> 10;
            if (buf < 2) {
                int r = (s >> 3) & 127;
                int c = s & 7;
                const __nv_bfloat16* src = buf ? A2 : A1;
                uint32_t dst = sb + st * 65536 + buf * 16384
                             + SWA((uint32_t)(r * 128 + c * 16));
                cp16(dst, src + (m0 + r) * 256 + k0 + c * 8);
            } else {
                int v2 = s & 1023;
                int kr = v2 >> 4;
                int c = v2 & 15;
                const __nv_bfloat16* src = (buf == 2) ? B1 : B2;
                uint32_t dst = sb + st * 65536 + buf * 16384
                             + SWB((uint32_t)(kr * 256 + c * 16));
                cp16(dst, src + (size_t)(k0 + kr) * HWN + n0 + c * 8);
            }
        }
        CP_COMMIT();
    };

    issue(0, 0);
    for (int ch = 0; ch < 4; ch++) {
        int st = ch & 1;
        if (ch + 1 < 4) { issue(ch + 1, st ^ 1); CP_WAIT_1(); }
        else            { CP_WAIT_0(); }
        __syncthreads();
        uint32_t stb = sb + st * 65536;
#pragma unroll
        for (int ks = 0; ks < 4; ks++) {
            int kb = (ks * 16 + koff) * 2;
            uint32_t a[4][4], bf[2][4], bf2[2][4];
#pragma unroll
            for (int g = 0; g < 2; g++) {
                uint32_t off = (uint32_t)((ks * 16 + frag_row) * 256
                                          + (wc * 32 + g * 16 + koff) * 2);
                ldm_x4_t(bf[g],  stb + 2 * 16384 + SWB(off));
                ldm_x4_t(bf2[g], stb + 3 * 16384 + SWB(off));
            }
#pragma unroll
            for (int mt = 0; mt < 4; mt++) {
                uint32_t off = (uint32_t)((wr * 64 + mt * 16 + frag_row) * 128 + kb);
                ldm_x4(a[mt], stb + SWA(off));
            }
#pragma unroll
            for (int mt = 0; mt < 4; mt++)
#pragma unroll
                for (int nt = 0; nt < 4; nt++) {
                    int g = nt >> 1, p = nt & 1;
                    mma_bf16(acc[mt][nt], a[mt], bf[g][p*2],  bf[g][p*2+1]);   // F1*b1
                    mma_bf16(acc[mt][nt], a[mt], bf2[g][p*2], bf2[g][p*2+1]);  // F1*b2
                }
#pragma unroll
            for (int mt = 0; mt < 4; mt++) {
                uint32_t off = (uint32_t)((wr * 64 + mt * 16 + frag_row) * 128 + kb);
                ldm_x4(a[mt], stb + 16384 + SWA(off));
            }
#pragma unroll
            for (int mt = 0; mt < 4; mt++)
#pragma unroll
                for (int nt = 0; nt < 4; nt++) {
                    int g = nt >> 1, p = nt & 1;
                    mma_bf16(acc[mt][nt], a[mt], bf[g][p*2], bf[g][p*2+1]);    // F2*b1
                }
        }
        __syncthreads();
    }
    // epilogue: + g[m] + x[m][n]
    const float* xb = x + (size_t)b * CHW;
    float* ob = out + (size_t)b * CHW;
#pragma unroll
    for (int mt = 0; mt < 4; mt++) {
        int row = m0 + wr * 64 + mt * 16 + (l >> 2);
        float g0 = d_g[b * 256 + row];
        float g1 = d_g[b * 256 + row + 8];
#pragma unroll
        for (int nt = 0; nt < 4; nt++) {
            int col = n0 + wc * 32 + nt * 8 + (l & 3) * 2;
            float2 s0 = *(const float2*)&xb[(size_t)row * HWN + col];
            float2 s1 = *(const float2*)&xb[(size_t)(row + 8) * HWN + col];
            float2 v0, v1;
            v0.x = acc[mt][nt][0] + g0 + s0.x;
            v0.y = acc[mt][nt][1] + g0 + s0.y;
            v1.x = acc[mt][nt][2] + g1 + s1.x;
            v1.y = acc[mt][nt][3] + g1 + s1.y;
            *(float2*)&ob[(size_t)row * HWN + col] = v0;
            *(float2*)&ob[(size_t)(row + 8) * HWN + col] = v1;
        }
    }
}

// ---------------- launch ----------------
extern "C" void kernel_launch(void* const* d_in, const int* in_sizes, int n_in,
                              void* d_out, int out_size) {
    const float* x    = (const float*)d_in[0];
    const float* gnw  = (const float*)d_in[1];
    const float* gnb  = (const float*)d_in[2];
    const float* qkvw = (const float*)d_in[3];
    const float* qkvb = (const float*)d_in[4];
    const float* outw = (const float*)d_in[5];
    const float* outb = (const float*)d_in[6];
    float* out = (float*)d_out;

    cudaFuncSetAttribute(gram_mma_kernel, cudaFuncAttributeMaxDynamicSharedMemorySize, 131072);
    cudaFuncSetAttribute(fgemm_kernel,    cudaFuncAttributeMaxDynamicSharedMemorySize, 131072);

    convstats_kernel<<<BATCH * CC, 256>>>(x);
    pack_kernel<<<6, 128>>>(qkvw, qkvb, gnb);
    groupstats_kernel<<<1, 128>>>(gnw);
    gram_mma_kernel<<<dim3(3, GSPLITS, BATCH), 256, 131072>>>();
    reduceG_kernel<<<1024, 256>>>();
    gemm64<0><<<dim3(4, 4, BATCH), 256>>>(nullptr);
    pvec_kernel<<<16, 128>>>();
    scores_kernel<<<BATCH * 64, 256>>>();
    softmax_kernel<<<BATCH, 512>>>();
    t_kernel<<<BATCH * 64, 256>>>(gnw);
    gemm64<1><<<dim3(4, 4, BATCH), 256>>>(outw);
    fold_kernel<<<BATCH, 256>>>(outw, outb);
    fgemm_kernel<<<dim3(2, HWN / 128, BATCH), 256, 131072>>>(x, out);
}

// round 9
// speedup vs baseline: 2.4054x; 1.0922x over previous
#include <cuda_runtime.h>
#include <cuda_bf16.h>
#include <math.h>
#include <stdint.h>

#define HWN   16384
#define CC    256
#define BATCH 4
#define CHW   (CC*HWN)
#define GSPLITS 12

// ---------------- scratch (static __device__, no allocations) ----------------
__device__ __align__(16) float d_Sx[BATCH*CC];
__device__ __align__(16) float d_Sxx[BATCH*CC];
__device__ __align__(16) float d_m[BATCH*CC];
__device__ __align__(16) float d_a[BATCH*CC];
__device__ __align__(16) float d_wa[BATCH*CC];
__device__ __align__(16) float d_rp[BATCH*CC];
__device__ __align__(16) float d_Wq[CC*CC];
__device__ __align__(16) float d_Wk[CC*CC];
__device__ __align__(16) float d_Wv[CC*CC];
__device__ __align__(16) float d_btq[CC];
__device__ __align__(16) float d_btk[CC];
__device__ __align__(16) float d_btv[CC];
__device__ __align__(16) __nv_bfloat16 d_b1[BATCH*CHW];        // 32 MB
__device__ __align__(16) __nv_bfloat16 d_b2[BATCH*CHW];        // 32 MB
__device__ __align__(16) float d_Gpart[BATCH*GSPLITS*CC*CC];
__device__ __align__(16) float d_G[BATCH*CC*CC];
__device__ __align__(16) float d_U[BATCH*CC*CC];
__device__ __align__(16) float d_pq[BATCH*CC];
__device__ __align__(16) float d_pk[BATCH*CC];
__device__ __align__(16) float d_sc[BATCH*64*16];
__device__ __align__(16) float d_Smx[BATCH*64*16];
__device__ __align__(16) float d_T[BATCH*CC*CC];
__device__ __align__(16) float d_tv[BATCH*CC];
__device__ __align__(16) float d_E[BATCH*CC*CC];
__device__ __align__(16) __nv_bfloat16 d_F1[BATCH*CC*CC];
__device__ __align__(16) float d_g[BATCH*CC];

// ---------------- mma / ldmatrix / cp.async helpers (baseline PTX, sm_80+) ----------------
__device__ __forceinline__ uint32_t smem_u32(const void* p) {
    uint32_t a;
    asm("{ .reg .u64 t; cvta.to.shared.u64 t, %1; cvt.u32.u64 %0, t; }" : "=r"(a) : "l"(p));
    return a;
}
__device__ __forceinline__ void ldm_x4(uint32_t* r, uint32_t addr) {
    asm volatile("ldmatrix.sync.aligned.m8n8.x4.shared.b16 {%0,%1,%2,%3}, [%4];"
                 : "=r"(r[0]), "=r"(r[1]), "=r"(r[2]), "=r"(r[3]) : "r"(addr));
}
__device__ __forceinline__ void ldm_x4_t(uint32_t* r, uint32_t addr) {
    asm volatile("ldmatrix.sync.aligned.m8n8.x4.trans.shared.b16 {%0,%1,%2,%3}, [%4];"
                 : "=r"(r[0]), "=r"(r[1]), "=r"(r[2]), "=r"(r[3]) : "r"(addr));
}
__device__ __forceinline__ void mma_bf16(float* c, const uint32_t* a,
                                         uint32_t b0, uint32_t b1) {
    asm volatile("mma.sync.aligned.m16n8k16.row.col.f32.bf16.bf16.f32 "
                 "{%0,%1,%2,%3}, {%4,%5,%6,%7}, {%8,%9}, {%0,%1,%2,%3};"
                 : "+f"(c[0]), "+f"(c[1]), "+f"(c[2]), "+f"(c[3])
                 : "r"(a[0]), "r"(a[1]), "r"(a[2]), "r"(a[3]), "r"(b0), "r"(b1));
}
__device__ __forceinline__ void cp16(uint32_t dst, const void* src) {
    asm volatile("cp.async.cg.shared.global [%0], [%1], 16;" :: "r"(dst), "l"(src) : "memory");
}
#define CP_COMMIT()  asm volatile("cp.async.commit_group;" ::: "memory")
#define CP_WAIT_1()  asm volatile("cp.async.wait_group 1;" ::: "memory")
#define CP_WAIT_0()  asm volatile("cp.async.wait_group 0;" ::: "memory")

#define SWA(o) ((o) ^ (((o) >> 3) & 0x70))
#define SWB(o) ((o) ^ ((((o) >> 8) & 7) << 4))

// ---------------- 1) fused convert + stats ----------------
__global__ void convstats_kernel(const float* __restrict__ x) {
    int bc = blockIdx.x;
    const float4* p = (const float4*)(x + (size_t)bc * HWN);
    uint2* o1 = (uint2*)(d_b1 + (size_t)bc * HWN);
    uint2* o2 = (uint2*)(d_b2 + (size_t)bc * HWN);
    float s = 0.f, s2 = 0.f;
    for (int i = threadIdx.x; i < HWN/4; i += 256) {
        float4 v = p[i];
        float in[4] = {v.x, v.y, v.z, v.w};
        uint32_t hh[4], ll[4];
#pragma unroll
        for (int j = 0; j < 4; j++) {
            s  += in[j];
            s2 += in[j] * in[j];
            __nv_bfloat16 h = __float2bfloat16(in[j]);
            float hf = __bfloat162float(h);
            __nv_bfloat16 lo = __float2bfloat16(in[j] - hf);
            hh[j] = (uint32_t)__bfloat16_as_ushort(h);
            ll[j] = (uint32_t)__bfloat16_as_ushort(lo);
        }
        uint2 ph; ph.x = hh[0] | (hh[1] << 16); ph.y = hh[2] | (hh[3] << 16);
        uint2 pl; pl.x = ll[0] | (ll[1] << 16); pl.y = ll[2] | (ll[3] << 16);
        o1[i] = ph; o2[i] = pl;
    }
    for (int o = 16; o; o >>= 1) {
        s  += __shfl_down_sync(0xffffffffu, s, o);
        s2 += __shfl_down_sync(0xffffffffu, s2, o);
    }
    __shared__ float sh[8][2];
    int w = threadIdx.x >> 5, l = threadIdx.x & 31;
    if (l == 0) { sh[w][0] = s; sh[w][1] = s2; }
    __syncthreads();
    if (threadIdx.x == 0) {
        float S = 0.f, S2 = 0.f;
        for (int i = 0; i < 8; i++) { S += sh[i][0]; S2 += sh[i][1]; }
        d_Sx[bc] = S; d_Sxx[bc] = S2;
    }
}

// ---------------- 2) pack qkv rows + fold gn_bias ----------------
__global__ void pack_kernel(const float* __restrict__ qkvw,
                            const float* __restrict__ qkvb,
                            const float* __restrict__ gnb) {
    int rid = blockIdx.x * 128 + threadIdx.x;
    if (rid >= 768) return;
    int sel = rid / 256;
    int p   = rid % 256;
    int h = p >> 2, dd = p & 3;
    int src = h * 12 + sel * 4 + dd;
    const float* wrow = qkvw + src * 256;
    float* dst = (sel == 0 ? d_Wq : (sel == 1 ? d_Wk : d_Wv)) + p * 256;
    float dot = 0.f;
    for (int c = 0; c < 256; c++) {
        float w = wrow[c];
        dst[c] = w;
        dot += w * gnb[c];
    }
    float bt = qkvb[src] + dot;
    if (sel == 0) d_btq[p] = bt; else if (sel == 1) d_btk[p] = bt; else d_btv[p] = bt;
}

// ---------------- 3) group stats ----------------
__global__ void groupstats_kernel(const float* __restrict__ gnw) {
    int t = threadIdx.x;
    if (t >= 128) return;
    int b = t >> 5, g = t & 31;
    float s = 0.f, s2 = 0.f;
    for (int c8 = 0; c8 < 8; c8++) {
        int idx = b * 256 + g * 8 + c8;
        s += d_Sx[idx]; s2 += d_Sxx[idx];
    }
    const float n = 8.f * (float)HWN;
    float mean = s / n;
    float var  = (s2 - n * mean * mean) / (n - 1.f);
    float a = rsqrtf(var + 1e-5f);
    for (int c8 = 0; c8 < 8; c8++) {
        int c = g * 8 + c8;
        int idx = b * 256 + c;
        d_m[idx] = mean;
        d_a[idx] = a;
        float wa = gnw[c] * a;
        d_wa[idx] = wa;
        d_rp[idx] = wa * (d_Sx[idx] - (float)HWN * mean);
    }
}

// ---------------- 4) HMMA Gram, 2-stage cp.async (3-product bf16 split) ----------------
__global__ void __launch_bounds__(256, 1) gram_mma_kernel() {
    extern __shared__ char sm[];
    int b = blockIdx.z, split = blockIdx.y, t = blockIdx.x;
    int i0 = (t == 2) ? 128 : 0;
    int j0 = (t == 0) ? 0 : 128;
    int nch = 21 + (split < 4 ? 1 : 0);
    int ch0 = split * 21 + (split < 4 ? split : 4);
    int tid = threadIdx.x, wid = tid >> 5, l = tid & 31;
    int wr = wid >> 2, wc = wid & 3;
    uint32_t sb = smem_u32(sm);

    float acc[4][4][4] = {};
    int frag_row = ((l >> 3) & 1) * 8 + (l & 7);
    int koff = (l >> 4) * 8;

    auto issue = [&](int ch, int st) {
        int k0 = (ch0 + ch) * 64;
#pragma unroll
        for (int it = 0; it < 16; it++) {
            int s = tid + it * 256;
            int buf = s >> 10;
            int r = (s >> 3) & 127;
            int c = s & 7;
            const __nv_bfloat16* base = ((buf & 1) ? d_b2 : d_b1)
                + (size_t)b * CHW + (size_t)((buf < 2) ? i0 : j0) * HWN;
            uint32_t dst = sb + st * 65536 + buf * 16384
                         + SWA((uint32_t)(r * 128 + c * 16));
            cp16(dst, base + (size_t)r * HWN + k0 + c * 8);
        }
        CP_COMMIT();
    };

    issue(0, 0);
    for (int ch = 0; ch < nch; ch++) {
        int st = ch & 1;
        if (ch + 1 < nch) { issue(ch + 1, st ^ 1); CP_WAIT_1(); }
        else              { CP_WAIT_0(); }
        __syncthreads();
        uint32_t stb = sb + st * 65536;
#pragma unroll
        for (int ks = 0; ks < 4; ks++) {
            int kb = (ks * 16 + koff) * 2;
            uint32_t a[4][4], bf[2][4], bf2[2][4];
#pragma unroll
            for (int g = 0; g < 2; g++) {
                uint32_t off = (uint32_t)((wc * 32 + g * 16 + frag_row) * 128 + kb);
                ldm_x4(bf[g],  stb + 2 * 16384 + SWA(off));
                ldm_x4(bf2[g], stb + 3 * 16384 + SWA(off));
            }
#pragma unroll
            for (int mt = 0; mt < 4; mt++) {
                uint32_t off = (uint32_t)((wr * 64 + mt * 16 + frag_row) * 128 + kb);
                ldm_x4(a[mt], stb + SWA(off));
            }
#pragma unroll
            for (int mt = 0; mt < 4; mt++)
#pragma unroll
                for (int nt = 0; nt < 4; nt++) {
                    int g = nt >> 1, p = nt & 1;
                    mma_bf16(acc[mt][nt], a[mt], bf[g][p],  bf[g][p + 2]);
                    mma_bf16(acc[mt][nt], a[mt], bf2[g][p], bf2[g][p + 2]);
                }
#pragma unroll
            for (int mt = 0; mt < 4; mt++) {
                uint32_t off = (uint32_t)((wr * 64 + mt * 16 + frag_row) * 128 + kb);
                ldm_x4(a[mt], stb + 16384 + SWA(off));
            }
#pragma unroll
            for (int mt = 0; mt < 4; mt++)
#pragma unroll
                for (int nt = 0; nt < 4; nt++) {
                    int g = nt >> 1, p = nt & 1;
                    mma_bf16(acc[mt][nt], a[mt], bf[g][p], bf[g][p + 2]);
                }
        }
        __syncthreads();
    }
    float* gp = d_Gpart + ((size_t)(b * GSPLITS + split)) * 65536;
#pragma unroll
    for (int mt = 0; mt < 4; mt++)
#pragma unroll
        for (int nt = 0; nt < 4; nt++) {
            int row = i0 + wr * 64 + mt * 16 + (l >> 2);
            int col = j0 + wc * 32 + nt * 8 + (l & 3) * 2;
            float2 v0; v0.x = acc[mt][nt][0]; v0.y = acc[mt][nt][1];
            float2 v1; v1.x = acc[mt][nt][2]; v1.y = acc[mt][nt][3];
            *(float2*)&gp[row * 256 + col] = v0;
            *(float2*)&gp[(row + 8) * 256 + col] = v1;
        }
}

// ---------------- 5) reduce partials (symmetry) + GN corrections -> G' ----------------
__global__ void reduceG_kernel() {
    int e = blockIdx.x * 256 + threadIdx.x;
    int b = e >> 16;
    int ij = e & 65535;
    int i = ij >> 8, j = ij & 255;
    int rij = (i >= 128 && j < 128) ? (j * 256 + i) : ij;
    size_t base = (size_t)b * GSPLITS * 65536 + rij;
    float sum = 0.f;
    for (int s = 0; s < GSPLITS; s++) sum += d_Gpart[base + (size_t)s * 65536];
    int bi = b * 256 + i, bj = b * 256 + j;
    float g = d_wa[bi] * d_wa[bj] *
              (sum - d_m[bi] * d_Sx[bj] - d_m[bj] * d_Sx[bi] + (float)HWN * d_m[bi] * d_m[bj]);
    d_G[e] = g;
}

// ---------------- small fp32 GEMMs (M=N=K=256) ----------------
template<int MODE>
__global__ void gemm64(const float* __restrict__ Aext) {
    int b = blockIdx.z;
    const float* A = (MODE == 0) ? d_Wq : Aext;
    const float* B = ((MODE == 0) ? d_G : d_T) + b * 65536;
    float* Cp = ((MODE == 0) ? d_U : d_E) + b * 65536;

    __shared__ float As[16][64];
    __shared__ float Bs[16][64];
    int m0 = blockIdx.x * 64, n0 = blockIdx.y * 64;
    int tid = threadIdx.x;
    int tx = tid & 15, ty = tid >> 4;
    int ar = tid >> 2, asg = tid & 3;
    int br = tid >> 4, bc = tid & 15;
    float acc[4][4] = {};
    for (int k0 = 0; k0 < 256; k0 += 16) {
        float4 av = *(const float4*)&A[(m0 + ar) * 256 + k0 + asg * 4];
        As[asg*4+0][ar] = av.x; As[asg*4+1][ar] = av.y; As[asg*4+2][ar] = av.z; As[asg*4+3][ar] = av.w;
        float4 bv = *(const float4*)&B[(k0 + br) * 256 + n0 + bc * 4];
        *(float4*)&Bs[br][bc * 4] = bv;
        __syncthreads();
#pragma unroll
        for (int kk = 0; kk < 16; kk++) {
            float4 a4 = *(const float4*)&As[kk][ty * 4];
            float4 b4 = *(const float4*)&Bs[kk][tx * 4];
            float avv[4] = {a4.x, a4.y, a4.z, a4.w};
            float bvv[4] = {b4.x, b4.y, b4.z, b4.w};
#pragma unroll
            for (int i = 0; i < 4; i++)
#pragma unroll
                for (int j = 0; j < 4; j++)
                    acc[i][j] += avv[i] * bvv[j];
        }
        __syncthreads();
    }
#pragma unroll
    for (int i = 0; i < 4; i++) {
        int m = m0 + ty * 4 + i;
        float4 v; v.x = acc[i][0]; v.y = acc[i][1]; v.z = acc[i][2]; v.w = acc[i][3];
        *(float4*)&Cp[m * 256 + n0 + tx * 4] = v;
    }
}

// ---------------- 6) p-vectors ----------------
__global__ void pvec_kernel() {
    int rid = blockIdx.x * 128 + threadIdx.x;
    if (rid >= 2048) return;
    int b = rid / 512;
    int q = rid % 512;
    int sel = q / 256, p = q % 256;
    const float* w = (sel ? d_Wk : d_Wq) + p * 256;
    const float* r = d_rp + b * 256;
    float s = 0.f;
    for (int c = 0; c < 256; c++) s += w[c] * r[c];
    (sel ? d_pk : d_pq)[b * 256 + p] = s;
}

// ---------------- 7) raw scores ----------------
__global__ void scores_kernel() {
    int bi = blockIdx.x;
    int b = bi >> 6, h = bi & 63;
    int tid = threadIdx.x;
    int pair = tid >> 4, l = tid & 15;
    int dd = pair >> 2, ee = pair & 3;
    int pU = h * 4 + dd, pK = h * 4 + ee;
    const float* u  = d_U + (size_t)b * 65536 + pU * 256;
    const float* wk = d_Wk + pK * 256;
    float s = 0.f;
    for (int c = l; c < 256; c += 16) s += u[c] * wk[c];
    for (int o = 8; o; o >>= 1) s += __shfl_down_sync(0xffffffffu, s, o, 16);
    if (l == 0) {
        s += d_pq[b * 256 + pU] * d_btk[pK]
           + d_btq[pU] * d_pk[b * 256 + pK]
           + (float)HWN * d_btq[pU] * d_btk[pK];
        d_sc[(b * 64 + h) * 16 + pair] = 0.5f * s;
    }
}

// ---------------- 8+9 fused) softmax over heads, then T = BD(S) Wv diag(gnw) ----------------
__global__ void softmax_t_kernel(const float* __restrict__ gnw) {
    int b = blockIdx.x;
    int tid = threadIdx.x;                 // 512 threads
    __shared__ float Ssh[64][16];
    {
        int w = tid >> 5;                  // pair 0..15
        int l = tid & 31;                  // heads l, l+32
        float v0 = d_sc[((b * 64 + l) << 4) + w];
        float v1 = d_sc[((b * 64 + l + 32) << 4) + w];
        float mx = fmaxf(v0, v1);
        for (int o = 16; o; o >>= 1) mx = fmaxf(mx, __shfl_xor_sync(0xffffffffu, mx, o));
        float e0 = expf(v0 - mx), e1 = expf(v1 - mx);
        float s = e0 + e1;
        for (int o = 16; o; o >>= 1) s += __shfl_xor_sync(0xffffffffu, s, o);
        Ssh[l][w] = e0 / s;
        Ssh[l + 32][w] = e1 / s;
    }
    __syncthreads();
    // T rows: p = h*4+dd (256 rows) x 256 cols; 512 threads -> each does 128 elems
    for (int e = tid; e < 65536; e += 512) {
        int p = e >> 8, c = e & 255;
        int h = p >> 2, dd = p & 3;
        const float* S = &Ssh[h][dd * 4];
        float s = S[0] * d_Wv[(h*4+0)*256 + c] + S[1] * d_Wv[(h*4+1)*256 + c]
                + S[2] * d_Wv[(h*4+2)*256 + c] + S[3] * d_Wv[(h*4+3)*256 + c];
        d_T[((size_t)b * 256 + p) * 256 + c] = gnw[c] * s;
    }
    if (tid < 256) {
        int h = tid >> 2, dd = tid & 3;
        float tv = 0.f;
        for (int e2 = 0; e2 < 4; e2++) tv += Ssh[h][dd * 4 + e2] * d_btv[h * 4 + e2];
        d_tv[b * 256 + tid] = tv;
    }
}

// ---------------- 10) fold: F = E diag(a) -> single bf16 ----------------
__global__ void fold_kernel(const float* __restrict__ outw,
                            const float* __restrict__ outb) {
    int b = blockIdx.x;
    int o = threadIdx.x;
    const float* ow = outw + o * 256;
    float e = outb[o];
    for (int p = 0; p < 256; p++) e += ow[p] * d_tv[b * 256 + p];
    float gacc = 0.f;
    for (int c = 0; c < 256; c++) {
        int idx = (b * 256 + o) * 256 + c;
        float f = d_E[idx] * d_a[b * 256 + c];
        d_F1[idx] = __float2bfloat16(f);
        gacc += f * d_m[b * 256 + c];
    }
    d_g[b * 256 + o] = e - gacc;
}

// ---------------- 11) HMMA final GEMM, single product, 2 CTA/SM: out = F@x + g + skip ----------------
__global__ void __launch_bounds__(256, 2) fgemm_kernel(const float* __restrict__ x,
                                                       float* __restrict__ out) {
    extern __shared__ char sm[];
    int b = blockIdx.z;
    int m0 = blockIdx.x * 128;
    int n0 = blockIdx.y * 128;
    int tid = threadIdx.x, wid = tid >> 5, l = tid & 31;
    int wr = wid >> 2, wc = wid & 3;
    uint32_t sb = smem_u32(sm);

    const __nv_bfloat16* A1 = d_F1 + b * 65536;
    const __nv_bfloat16* B1 = d_b1 + (size_t)b * CHW;

    float acc[4][4][4] = {};
    int frag_row = ((l >> 3) & 1) * 8 + (l & 7);
    int koff = (l >> 4) * 8;

    // stage: A 16KB (128 rows x 64 k) + B 16KB (64 k x 128 n); 2 stages = 64KB
    auto issue = [&](int ch, int st) {
        int k0 = ch * 64;
#pragma unroll
        for (int it = 0; it < 8; it++) {
            int s = tid + it * 256;          // 0..2047
            if (s < 1024) {                  // A
                int r = s >> 3;
                int c = s & 7;
                uint32_t dst = sb + st * 32768 + SWA((uint32_t)(r * 128 + c * 16));
                cp16(dst, A1 + (m0 + r) * 256 + k0 + c * 8);
            } else {                         // B
                int v2 = s & 1023;
                int kr = v2 >> 4;
                int c = v2 & 15;
                uint32_t dst = sb + st * 32768 + 16384 + SWB((uint32_t)(kr * 256 + c * 16));
                cp16(dst, B1 + (size_t)(k0 + kr) * HWN + n0 + c * 8);
            }
        }
        CP_COMMIT();
    };

    issue(0, 0);
    for (int ch = 0; ch < 4; ch++) {
        int st = ch & 1;
        if (ch + 1 < 4) { issue(ch + 1, st ^ 1); CP_WAIT_1(); }
        else            { CP_WAIT_0(); }
        __syncthreads();
        uint32_t stb = sb + st * 32768;
#pragma unroll
        for (int ks = 0; ks < 4; ks++) {
            int kb = (ks * 16 + koff) * 2;
            uint32_t a[4][4], bf[2][4];
#pragma unroll
            for (int g = 0; g < 2; g++) {
                uint32_t off = (uint32_t)((ks * 16 + frag_row) * 256
                                          + (wc * 32 + g * 16 + koff) * 2);
                ldm_x4_t(bf[g], stb + 16384 + SWB(off));
            }
#pragma unroll
            for (int mt = 0; mt < 4; mt++) {
                uint32_t off = (uint32_t)((wr * 64 + mt * 16 + frag_row) * 128 + kb);
                ldm_x4(a[mt], stb + SWA(off));
            }
#pragma unroll
            for (int mt = 0; mt < 4; mt++)
#pragma unroll
                for (int nt = 0; nt < 4; nt++) {
                    int g = nt >> 1, p = nt & 1;
                    mma_bf16(acc[mt][nt], a[mt], bf[g][p*2], bf[g][p*2+1]);
                }
        }
        __syncthreads();
    }
    // epilogue: + g[m] + x[m][n]
    const float* xb = x + (size_t)b * CHW;
    float* ob = out + (size_t)b * CHW;
#pragma unroll
    for (int mt = 0; mt < 4; mt++) {
        int row = m0 + wr * 64 + mt * 16 + (l >> 2);
        float g0 = d_g[b * 256 + row];
        float g1 = d_g[b * 256 + row + 8];
#pragma unroll
        for (int nt = 0; nt < 4; nt++) {
            int col = n0 + wc * 32 + nt * 8 + (l & 3) * 2;
            float2 s0 = *(const float2*)&xb[(size_t)row * HWN + col];
            float2 s1 = *(const float2*)&xb[(size_t)(row + 8) * HWN + col];
            float2 v0, v1;
            v0.x = acc[mt][nt][0] + g0 + s0.x;
            v0.y = acc[mt][nt][1] + g0 + s0.y;
            v1.x = acc[mt][nt][2] + g1 + s1.x;
            v1.y = acc[mt][nt][3] + g1 + s1.y;
            *(float2*)&ob[(size_t)row * HWN + col] = v0;
            *(float2*)&ob[(size_t)(row + 8) * HWN + col] = v1;
        }
    }
}

// ---------------- launch ----------------
extern "C" void kernel_launch(void* const* d_in, const int* in_sizes, int n_in,
                              void* d_out, int out_size) {
    const float* x    = (const float*)d_in[0];
    const float* gnw  = (const float*)d_in[1];
    const float* gnb  = (const float*)d_in[2];
    const float* qkvw = (const float*)d_in[3];
    const float* qkvb = (const float*)d_in[4];
    const float* outw = (const float*)d_in[5];
    const float* outb = (const float*)d_in[6];
    float* out = (float*)d_out;

    cudaFuncSetAttribute(gram_mma_kernel, cudaFuncAttributeMaxDynamicSharedMemorySize, 131072);
    cudaFuncSetAttribute(fgemm_kernel,    cudaFuncAttributeMaxDynamicSharedMemorySize, 65536);

    convstats_kernel<<<BATCH * CC, 256>>>(x);
    pack_kernel<<<6, 128>>>(qkvw, qkvb, gnb);
    groupstats_kernel<<<1, 128>>>(gnw);
    gram_mma_kernel<<<dim3(3, GSPLITS, BATCH), 256, 131072>>>();
    reduceG_kernel<<<1024, 256>>>();
    gemm64<0><<<dim3(4, 4, BATCH), 256>>>(nullptr);
    pvec_kernel<<<16, 128>>>();
    scores_kernel<<<BATCH * 64, 256>>>();
    softmax_t_kernel<<<BATCH, 512>>>(gnw);
    gemm64<1><<<dim3(4, 4, BATCH), 256>>>(outw);
    fold_kernel<<<BATCH, 256>>>(outw, outb);
    fgemm_kernel<<<dim3(2, HWN / 128, BATCH), 256, 65536>>>(x, out);
}

// round 10
// speedup vs baseline: 2.5956x; 1.0791x over previous
#include <cuda_runtime.h>
#include <cuda_bf16.h>
#include <math.h>
#include <stdint.h>

#define HWN   16384
#define CC    256
#define BATCH 4
#define CHW   (CC*HWN)
#define GS    10        // gram split-K

// ---------------- scratch (static __device__, no allocations) ----------------
__device__ __align__(16) float d_Sx[BATCH*CC];
__device__ __align__(16) float d_Sxx[BATCH*CC];
__device__ __align__(16) float d_m[BATCH*CC];
__device__ __align__(16) float d_a[BATCH*CC];
__device__ __align__(16) float d_wa[BATCH*CC];
__device__ __align__(16) float d_rp[BATCH*CC];
__device__ __align__(16) float d_Wq[CC*CC];
__device__ __align__(16) float d_Wk[CC*CC];
__device__ __align__(16) float d_Wv[CC*CC];
__device__ __align__(16) float d_btq[CC];
__device__ __align__(16) float d_btk[CC];
__device__ __align__(16) float d_btv[CC];
__device__ __align__(16) __nv_bfloat16 d_b1[BATCH*CHW];   // 32 MB
__device__ __align__(16) __nv_bfloat16 d_b2[BATCH*CHW];   // 32 MB
__device__ __align__(16) float d_Gp[7*GS*BATCH*128*128];  // per-split tile partials
__device__ __align__(16) float d_Gs[7*BATCH*128*128];     // split-summed tiles
__device__ __align__(16) float d_G[BATCH*CC*CC];
__device__ __align__(16) float d_sc[BATCH*64*16];
__device__ __align__(16) float d_T[BATCH*CC*CC];
__device__ __align__(16) __nv_bfloat16 d_F1[BATCH*CC*CC];
__device__ __align__(16) float d_g[BATCH*CC];

// ---------------- mma / ldmatrix / cp.async helpers (baseline PTX, sm_80+) ----------------
__device__ __forceinline__ uint32_t smem_u32(const void* p) {
    uint32_t a;
    asm("{ .reg .u64 t; cvta.to.shared.u64 t, %1; cvt.u32.u64 %0, t; }" : "=r"(a) : "l"(p));
    return a;
}
__device__ __forceinline__ void ldm_x4(uint32_t* r, uint32_t addr) {
    asm volatile("ldmatrix.sync.aligned.m8n8.x4.shared.b16 {%0,%1,%2,%3}, [%4];"
                 : "=r"(r[0]), "=r"(r[1]), "=r"(r[2]), "=r"(r[3]) : "r"(addr));
}
__device__ __forceinline__ void ldm_x4_t(uint32_t* r, uint32_t addr) {
    asm volatile("ldmatrix.sync.aligned.m8n8.x4.trans.shared.b16 {%0,%1,%2,%3}, [%4];"
                 : "=r"(r[0]), "=r"(r[1]), "=r"(r[2]), "=r"(r[3]) : "r"(addr));
}
__device__ __forceinline__ void mma_bf16(float* c, const uint32_t* a,
                                         uint32_t b0, uint32_t b1) {
    asm volatile("mma.sync.aligned.m16n8k16.row.col.f32.bf16.bf16.f32 "
                 "{%0,%1,%2,%3}, {%4,%5,%6,%7}, {%8,%9}, {%0,%1,%2,%3};"
                 : "+f"(c[0]), "+f"(c[1]), "+f"(c[2]), "+f"(c[3])
                 : "r"(a[0]), "r"(a[1]), "r"(a[2]), "r"(a[3]), "r"(b0), "r"(b1));
}
__device__ __forceinline__ void cp16(uint32_t dst, const void* src) {
    asm volatile("cp.async.cg.shared.global [%0], [%1], 16;" :: "r"(dst), "l"(src) : "memory");
}
#define CP_COMMIT()  asm volatile("cp.async.commit_group;" ::: "memory")
#define CP_WAIT_2()  asm volatile("cp.async.wait_group 2;" ::: "memory")
#define CP_WAIT_1()  asm volatile("cp.async.wait_group 1;" ::: "memory")
#define CP_WAIT_0()  asm volatile("cp.async.wait_group 0;" ::: "memory")

#define SWA(o) ((o) ^ (((o) >> 3) & 0x70))
#define SWB(o) ((o) ^ ((((o) >> 8) & 7) << 4))

// ---------------- 1) fused convert + stats ----------------
__global__ void convstats_kernel(const float* __restrict__ x) {
    int bc = blockIdx.x;
    const float4* p = (const float4*)(x + (size_t)bc * HWN);
    uint2* o1 = (uint2*)(d_b1 + (size_t)bc * HWN);
    uint2* o2 = (uint2*)(d_b2 + (size_t)bc * HWN);
    float s = 0.f, s2 = 0.f;
    for (int i = threadIdx.x; i < HWN/4; i += 256) {
        float4 v = p[i];
        float in[4] = {v.x, v.y, v.z, v.w};
        uint32_t hh[4], ll[4];
#pragma unroll
        for (int j = 0; j < 4; j++) {
            s  += in[j];
            s2 += in[j] * in[j];
            __nv_bfloat16 h = __float2bfloat16(in[j]);
            float hf = __bfloat162float(h);
            __nv_bfloat16 lo = __float2bfloat16(in[j] - hf);
            hh[j] = (uint32_t)__bfloat16_as_ushort(h);
            ll[j] = (uint32_t)__bfloat16_as_ushort(lo);
        }
        uint2 ph; ph.x = hh[0] | (hh[1] << 16); ph.y = hh[2] | (hh[3] << 16);
        uint2 pl; pl.x = ll[0] | (ll[1] << 16); pl.y = ll[2] | (ll[3] << 16);
        o1[i] = ph; o2[i] = pl;
    }
    for (int o = 16; o; o >>= 1) {
        s  += __shfl_down_sync(0xffffffffu, s, o);
        s2 += __shfl_down_sync(0xffffffffu, s2, o);
    }
    __shared__ float sh[8][2];
    int w = threadIdx.x >> 5, l = threadIdx.x & 31;
    if (l == 0) { sh[w][0] = s; sh[w][1] = s2; }
    __syncthreads();
    if (threadIdx.x == 0) {
        float S = 0.f, S2 = 0.f;
        for (int i = 0; i < 8; i++) { S += sh[i][0]; S2 += sh[i][1]; }
        d_Sx[bc] = S; d_Sxx[bc] = S2;
    }
}

// ---------------- 2) prep = pack(blocks 0-5) + groupstats(block 6) ----------------
__global__ void prep_kernel(const float* __restrict__ qkvw,
                            const float* __restrict__ qkvb,
                            const float* __restrict__ gnb,
                            const float* __restrict__ gnw) {
    if (blockIdx.x < 6) {
        int rid = blockIdx.x * 128 + threadIdx.x;     // 0..767
        int sel = rid / 256;
        int p   = rid % 256;
        int h = p >> 2, dd = p & 3;
        int src = h * 12 + sel * 4 + dd;
        const float* wrow = qkvw + src * 256;
        float* dst = (sel == 0 ? d_Wq : (sel == 1 ? d_Wk : d_Wv)) + p * 256;
        float dot = 0.f;
        for (int c = 0; c < 256; c++) {
            float w = wrow[c];
            dst[c] = w;
            dot += w * gnb[c];
        }
        float bt = qkvb[src] + dot;
        if (sel == 0) d_btq[p] = bt; else if (sel == 1) d_btk[p] = bt; else d_btv[p] = bt;
    } else {
        int t = threadIdx.x;             // 0..127 = (b,g)
        int b = t >> 5, g = t & 31;
        float s = 0.f, s2 = 0.f;
        for (int c8 = 0; c8 < 8; c8++) {
            int idx = b * 256 + g * 8 + c8;
            s += d_Sx[idx]; s2 += d_Sxx[idx];
        }
        const float n = 8.f * (float)HWN;
        float mean = s / n;
        float var  = (s2 - n * mean * mean) / (n - 1.f);
        float a = rsqrtf(var + 1e-5f);
        for (int c8 = 0; c8 < 8; c8++) {
            int c = g * 8 + c8;
            int idx = b * 256 + c;
            d_m[idx] = mean;
            d_a[idx] = a;
            float wa = gnw[c] * a;
            d_wa[idx] = wa;
            d_rp[idx] = wa * (d_Sx[idx] - (float)HWN * mean);
        }
    }
}

// ---------------- 3) HMMA Gram tiles: 7 single-product jobs, 3-stage pipeline ----------------
// jid 0..2: P = b1_i b1_j^T, (ti,tj) in {(0,0),(0,1),(1,1)}
// jid 3..6: M = b1_i b2_j^T, (ti,tj) = ((jid-3)>>1, (jid-3)&1)
__global__ void __launch_bounds__(256, 2) gram_mma_kernel() {
    extern __shared__ char sm[];
    int b = blockIdx.z, split = blockIdx.y, jid = blockIdx.x;
    int ti, tj;
    const __nv_bfloat16* Bbase;
    if (jid < 3) { ti = (jid == 2) ? 1 : 0; tj = (jid == 0) ? 0 : 1; Bbase = d_b1; }
    else { int j2 = jid - 3; ti = j2 >> 1; tj = j2 & 1; Bbase = d_b2; }
    int nch = 25 + (split < 6 ? 1 : 0);
    int ch0 = split * 25 + (split < 6 ? split : 6);
    int tid = threadIdx.x, wid = tid >> 5, l = tid & 31;
    int wr = wid >> 2, wc = wid & 3;
    uint32_t sb = smem_u32(sm);

    const __nv_bfloat16* Ap = d_b1  + (size_t)b * CHW + (size_t)(ti * 128) * HWN;
    const __nv_bfloat16* Bp = Bbase + (size_t)b * CHW + (size_t)(tj * 128) * HWN;

    float acc[4][4][4] = {};
    int frag_row = ((l >> 3) & 1) * 8 + (l & 7);
    int koff = (l >> 4) * 8;

    auto issue = [&](int ch, int st) {
        int k0 = (ch0 + ch) * 64;
#pragma unroll
        for (int it = 0; it < 8; it++) {
            int s = tid + it * 256;          // 0..2047
            int buf = s >> 10;
            int r = (s >> 3) & 127;
            int c = s & 7;
            const __nv_bfloat16* src = buf ? Bp : Ap;
            uint32_t dst = sb + st * 32768 + buf * 16384
                         + SWA((uint32_t)(r * 128 + c * 16));
            cp16(dst, src + (size_t)r * HWN + k0 + c * 8);
        }
        CP_COMMIT();
    };

    issue(0, 0);
    issue(1, 1);
    for (int ch = 0; ch < nch; ch++) {
        int st = ch % 3;
        if (ch + 2 < nch)      { issue(ch + 2, (ch + 2) % 3); CP_WAIT_2(); }
        else if (ch + 1 < nch) { CP_WAIT_1(); }
        else                   { CP_WAIT_0(); }
        __syncthreads();
        uint32_t stb = sb + st * 32768;
#pragma unroll
        for (int ks = 0; ks < 4; ks++) {
            int kb = (ks * 16 + koff) * 2;
            uint32_t a[4][4], bf[2][4];
#pragma unroll
            for (int g = 0; g < 2; g++) {
                uint32_t off = (uint32_t)((wc * 32 + g * 16 + frag_row) * 128 + kb);
                ldm_x4(bf[g], stb + 16384 + SWA(off));
            }
#pragma unroll
            for (int mt = 0; mt < 4; mt++) {
                uint32_t off = (uint32_t)((wr * 64 + mt * 16 + frag_row) * 128 + kb);
                ldm_x4(a[mt], stb + SWA(off));
            }
#pragma unroll
            for (int mt = 0; mt < 4; mt++)
#pragma unroll
                for (int nt = 0; nt < 4; nt++) {
                    int g = nt >> 1, p = nt & 1;
                    mma_bf16(acc[mt][nt], a[mt], bf[g][p], bf[g][p + 2]);
                }
        }
        __syncthreads();
    }
    float* gp = d_Gp + ((size_t)((jid * GS + split) * BATCH + b)) * 16384;
#pragma unroll
    for (int mt = 0; mt < 4; mt++)
#pragma unroll
        for (int nt = 0; nt < 4; nt++) {
            int row = wr * 64 + mt * 16 + (l >> 2);
            int col = wc * 32 + nt * 8 + (l & 3) * 2;
            float2 v0; v0.x = acc[mt][nt][0]; v0.y = acc[mt][nt][1];
            float2 v1; v1.x = acc[mt][nt][2]; v1.y = acc[mt][nt][3];
            *(float2*)&gp[row * 128 + col] = v0;
            *(float2*)&gp[(row + 8) * 128 + col] = v1;
        }
}

// ---------------- 4) sum over splits (coalesced) ----------------
__global__ void sumG_kernel() {
    int o = blockIdx.x * 256 + threadIdx.x;     // < 7*4*16384 = 458752
    int j = o >> 16;                            // job
    int rb = o & 65535;                         // b*16384 + e
    size_t base = (size_t)j * GS * BATCH * 16384 + rb;
    float s = 0.f;
    for (int sp = 0; sp < GS; sp++) s += d_Gp[base + (size_t)sp * BATCH * 16384];
    d_Gs[o] = s;
}

// ---------------- 5) combine P + M + M^T + GN corrections -> G' ----------------
__global__ void combineG_kernel() {
    int idx = blockIdx.x * 256 + threadIdx.x;   // < 4*65536
    int b = idx >> 16;
    int ij = idx & 65535;
    int i = ij >> 8, j = ij & 255;
    int hi = i >> 7, hj = j >> 7, il = i & 127, jl = j & 127;
    int pj = hi + hj;                            // 0,1,2
    int pe = (hi <= hj) ? (il * 128 + jl) : (jl * 128 + il);
    float sum = d_Gs[(pj * 4 + b) * 16384 + pe]
              + d_Gs[((3 + hi * 2 + hj) * 4 + b) * 16384 + il * 128 + jl]
              + d_Gs[((3 + hj * 2 + hi) * 4 + b) * 16384 + jl * 128 + il];
    int bi = b * 256 + i, bj = b * 256 + j;
    float g = d_wa[bi] * d_wa[bj] *
              (sum - d_m[bi] * d_Sx[bj] - d_m[bj] * d_Sx[bi] + (float)HWN * d_m[bi] * d_m[bj]);
    d_G[idx] = g;
}

// ---------------- 6) per-head scores: 4x4 block-diag of Wq G' Wk^T + corrections ----------------
__global__ void headscores_kernel() {
    int h = blockIdx.x, b = blockIdx.y;
    int tid = threadIdx.x;                        // 256
    __shared__ float wq_s[1024], wk_s[1024];
    __shared__ float red[8][24], fin[24];
    for (int i = tid; i < 1024; i += 256) {
        wq_s[i] = d_Wq[h * 1024 + i];
        wk_s[i] = d_Wk[h * 1024 + i];
    }
    __syncthreads();
    int c = tid;
    float v1[4] = {};
    const float* Gb = d_G + b * 65536;
    for (int p = 0; p < 256; p++) {
        float g = Gb[p * 256 + c];
        v1[0] += wq_s[p] * g;
        v1[1] += wq_s[256 + p] * g;
        v1[2] += wq_s[512 + p] * g;
        v1[3] += wq_s[768 + p] * g;
    }
    float rp = d_rp[b * 256 + c];
    float part[24];
#pragma unroll
    for (int d = 0; d < 4; d++)
#pragma unroll
        for (int e = 0; e < 4; e++)
            part[d * 4 + e] = v1[d] * wk_s[e * 256 + c];
#pragma unroll
    for (int d = 0; d < 4; d++) part[16 + d] = wq_s[d * 256 + c] * rp;
#pragma unroll
    for (int e = 0; e < 4; e++) part[20 + e] = wk_s[e * 256 + c] * rp;
#pragma unroll
    for (int k = 0; k < 24; k++)
        for (int o = 16; o; o >>= 1)
            part[k] += __shfl_down_sync(0xffffffffu, part[k], o);
    int wd = tid >> 5, ln = tid & 31;
    if (ln == 0)
#pragma unroll
        for (int k = 0; k < 24; k++) red[wd][k] = part[k];
    __syncthreads();
    if (tid < 24) {
        float s = 0.f;
        for (int w = 0; w < 8; w++) s += red[w][tid];
        fin[tid] = s;
    }
    __syncthreads();
    if (tid < 16) {
        int d = tid >> 2, e = tid & 3;
        float s = fin[tid]
                + fin[16 + d] * d_btk[h * 4 + e]
                + d_btq[h * 4 + d] * fin[20 + e]
                + (float)HWN * d_btq[h * 4 + d] * d_btk[h * 4 + e];
        d_sc[(b * 64 + h) * 16 + tid] = 0.5f * s;
    }
}

// ---------------- 7) softmax + T + u + g base ----------------
__global__ void softmax_t_kernel(const float* __restrict__ gnw,
                                 const float* __restrict__ outw,
                                 const float* __restrict__ outb) {
    int b = blockIdx.x;
    int tid = threadIdx.x;                 // 512
    __shared__ float Ssh[64][16];
    __shared__ float amsh[256], tvsh[256], ush[256], tmush[256];
    {
        int w = tid >> 5;                  // pair 0..15
        int l = tid & 31;
        float v0 = d_sc[((b * 64 + l) << 4) + w];
        float v1 = d_sc[((b * 64 + l + 32) << 4) + w];
        float mx = fmaxf(v0, v1);
        for (int o = 16; o; o >>= 1) mx = fmaxf(mx, __shfl_xor_sync(0xffffffffu, mx, o));
        float e0 = expf(v0 - mx), e1 = expf(v1 - mx);
        float s = e0 + e1;
        for (int o = 16; o; o >>= 1) s += __shfl_xor_sync(0xffffffffu, s, o);
        Ssh[l][w] = e0 / s;
        Ssh[l + 32][w] = e1 / s;
    }
    if (tid < 256) amsh[tid] = d_a[b * 256 + tid] * d_m[b * 256 + tid];
    __syncthreads();
    // T = BlockDiag(S) Wv diag(gnw)
    for (int e = tid; e < 65536; e += 512) {
        int p = e >> 8, c = e & 255;
        int h = p >> 2, dd = p & 3;
        const float* S = &Ssh[h][dd * 4];
        float s = S[0] * d_Wv[(h*4+0)*256 + c] + S[1] * d_Wv[(h*4+1)*256 + c]
                + S[2] * d_Wv[(h*4+2)*256 + c] + S[3] * d_Wv[(h*4+3)*256 + c];
        d_T[((size_t)b * 256 + p) * 256 + c] = gnw[c] * s;
    }
    if (tid < 256) {
        int h = tid >> 2, dd = tid & 3;
        float tv = 0.f;
        for (int e2 = 0; e2 < 4; e2++) tv += Ssh[h][dd * 4 + e2] * d_btv[h * 4 + e2];
        tvsh[tid] = tv;
    }
    __syncthreads();
    // u[p] = sum_c T[p][c] * a[c] * m[c]   (2 threads per p)
    {
        int p = tid >> 1, half = tid & 1;
        const float* Trow = d_T + ((size_t)b * 256 + p) * 256 + half * 128;
        const float* am = amsh + half * 128;
        float u = 0.f;
        for (int c = 0; c < 128; c++) u += Trow[c] * am[c];
        u += __shfl_down_sync(0xffffffffu, u, 1);
        if (!half) ush[p] = u;
    }
    __syncthreads();
    if (tid < 256) tmush[tid] = tvsh[tid] - ush[tid];
    __syncthreads();
    // g[o] = outb[o] + out_w[o,:] . (tv - u)
    if (tid < 256) {
        float g = outb[tid];
        const float* ow = outw + tid * 256;
        for (int p = 0; p < 256; p++) g += ow[p] * tmush[p];
        d_g[b * 256 + tid] = g;
    }
}

// ---------------- 8) E-GEMM: F1 = bf16( (out_w @ T) * diag(a) ) ----------------
__global__ void egemm_kernel(const float* __restrict__ outw) {
    int b = blockIdx.z;
    const float* A = outw;
    const float* B = d_T + b * 65536;

    __shared__ float As[16][64];
    __shared__ float Bs[16][64];
    int m0 = blockIdx.x * 64, n0 = blockIdx.y * 64;
    int tid = threadIdx.x;
    int tx = tid & 15, ty = tid >> 4;
    int ar = tid >> 2, asg = tid & 3;
    int br = tid >> 4, bc = tid & 15;
    float acc[4][4] = {};
    for (int k0 = 0; k0 < 256; k0 += 16) {
        float4 av = *(const float4*)&A[(m0 + ar) * 256 + k0 + asg * 4];
        As[asg*4+0][ar] = av.x; As[asg*4+1][ar] = av.y; As[asg*4+2][ar] = av.z; As[asg*4+3][ar] = av.w;
        float4 bv = *(const float4*)&B[(k0 + br) * 256 + n0 + bc * 4];
        *(float4*)&Bs[br][bc * 4] = bv;
        __syncthreads();
#pragma unroll
        for (int kk = 0; kk < 16; kk++) {
            float4 a4 = *(const float4*)&As[kk][ty * 4];
            float4 b4 = *(const float4*)&Bs[kk][tx * 4];
            float avv[4] = {a4.x, a4.y, a4.z, a4.w};
            float bvv[4] = {b4.x, b4.y, b4.z, b4.w};
#pragma unroll
            for (int i = 0; i < 4; i++)
#pragma unroll
                for (int j = 0; j < 4; j++)
                    acc[i][j] += avv[i] * bvv[j];
        }
        __syncthreads();
    }
    int colb = n0 + tx * 4;
    float a0 = d_a[b * 256 + colb + 0];
    float a1 = d_a[b * 256 + colb + 1];
    float a2 = d_a[b * 256 + colb + 2];
    float a3 = d_a[b * 256 + colb + 3];
#pragma unroll
    for (int i = 0; i < 4; i++) {
        int m = m0 + ty * 4 + i;
        uint32_t h0 = (uint32_t)__bfloat16_as_ushort(__float2bfloat16(acc[i][0] * a0));
        uint32_t h1 = (uint32_t)__bfloat16_as_ushort(__float2bfloat16(acc[i][1] * a1));
        uint32_t h2 = (uint32_t)__bfloat16_as_ushort(__float2bfloat16(acc[i][2] * a2));
        uint32_t h3 = (uint32_t)__bfloat16_as_ushort(__float2bfloat16(acc[i][3] * a3));
        uint2 v; v.x = h0 | (h1 << 16); v.y = h2 | (h3 << 16);
        *(uint2*)&d_F1[(size_t)(b * 256 + m) * 256 + colb] = v;
    }
}

// ---------------- 9) HMMA final GEMM: out = F@x + g + skip ----------------
__global__ void __launch_bounds__(256, 2) fgemm_kernel(const float* __restrict__ x,
                                                       float* __restrict__ out) {
    extern __shared__ char sm[];
    int b = blockIdx.z;
    int m0 = blockIdx.x * 128;
    int n0 = blockIdx.y * 128;
    int tid = threadIdx.x, wid = tid >> 5, l = tid & 31;
    int wr = wid >> 2, wc = wid & 3;
    uint32_t sb = smem_u32(sm);

    const __nv_bfloat16* A1 = d_F1 + b * 65536;
    const __nv_bfloat16* B1 = d_b1 + (size_t)b * CHW;

    float acc[4][4][4] = {};
    int frag_row = ((l >> 3) & 1) * 8 + (l & 7);
    int koff = (l >> 4) * 8;

    auto issue = [&](int ch, int st) {
        int k0 = ch * 64;
#pragma unroll
        for (int it = 0; it < 8; it++) {
            int s = tid + it * 256;          // 0..2047
            if (s < 1024) {                  // A
                int r = s >> 3;
                int c = s & 7;
                uint32_t dst = sb + st * 32768 + SWA((uint32_t)(r * 128 + c * 16));
                cp16(dst, A1 + (m0 + r) * 256 + k0 + c * 8);
            } else {                         // B
                int v2 = s & 1023;
                int kr = v2 >> 4;
                int c = v2 & 15;
                uint32_t dst = sb + st * 32768 + 16384 + SWB((uint32_t)(kr * 256 + c * 16));
                cp16(dst, B1 + (size_t)(k0 + kr) * HWN + n0 + c * 8);
            }
        }
        CP_COMMIT();
    };

    issue(0, 0);
    for (int ch = 0; ch < 4; ch++) {
        int st = ch & 1;
        if (ch + 1 < 4) { issue(ch + 1, st ^ 1); CP_WAIT_1(); }
        else            { CP_WAIT_0(); }
        __syncthreads();
        uint32_t stb = sb + st * 32768;
#pragma unroll
        for (int ks = 0; ks < 4; ks++) {
            int kb = (ks * 16 + koff) * 2;
            uint32_t a[4][4], bf[2][4];
#pragma unroll
            for (int g = 0; g < 2; g++) {
                uint32_t off = (uint32_t)((ks * 16 + frag_row) * 256
                                          + (wc * 32 + g * 16 + koff) * 2);
                ldm_x4_t(bf[g], stb + 16384 + SWB(off));
            }
#pragma unroll
            for (int mt = 0; mt < 4; mt++) {
                uint32_t off = (uint32_t)((wr * 64 + mt * 16 + frag_row) * 128 + kb);
                ldm_x4(a[mt], stb + SWA(off));
            }
#pragma unroll
            for (int mt = 0; mt < 4; mt++)
#pragma unroll
                for (int nt = 0; nt < 4; nt++) {
                    int g = nt >> 1, p = nt & 1;
                    mma_bf16(acc[mt][nt], a[mt], bf[g][p*2], bf[g][p*2+1]);
                }
        }
        __syncthreads();
    }
    const float* xb = x + (size_t)b * CHW;
    float* ob = out + (size_t)b * CHW;
#pragma unroll
    for (int mt = 0; mt < 4; mt++) {
        int row = m0 + wr * 64 + mt * 16 + (l >> 2);
        float g0 = d_g[b * 256 + row];
        float g1 = d_g[b * 256 + row + 8];
#pragma unroll
        for (int nt = 0; nt < 4; nt++) {
            int col = n0 + wc * 32 + nt * 8 + (l & 3) * 2;
            float2 s0 = *(const float2*)&xb[(size_t)row * HWN + col];
            float2 s1 = *(const float2*)&xb[(size_t)(row + 8) * HWN + col];
            float2 v0, v1;
            v0.x = acc[mt][nt][0] + g0 + s0.x;
            v0.y = acc[mt][nt][1] + g0 + s0.y;
            v1.x = acc[mt][nt][2] + g1 + s1.x;
            v1.y = acc[mt][nt][3] + g1 + s1.y;
            *(float2*)&ob[(size_t)row * HWN + col] = v0;
            *(float2*)&ob[(size_t)(row + 8) * HWN + col] = v1;
        }
    }
}

// ---------------- launch ----------------
extern "C" void kernel_launch(void* const* d_in, const int* in_sizes, int n_in,
                              void* d_out, int out_size) {
    const float* x    = (const float*)d_in[0];
    const float* gnw  = (const float*)d_in[1];
    const float* gnb  = (const float*)d_in[2];
    const float* qkvw = (const float*)d_in[3];
    const float* qkvb = (const float*)d_in[4];
    const float* outw = (const float*)d_in[5];
    const float* outb = (const float*)d_in[6];
    float* out = (float*)d_out;

    cudaFuncSetAttribute(gram_mma_kernel, cudaFuncAttributeMaxDynamicSharedMemorySize, 98304);
    cudaFuncSetAttribute(fgemm_kernel,    cudaFuncAttributeMaxDynamicSharedMemorySize, 65536);

    convstats_kernel<<<BATCH * CC, 256>>>(x);
    prep_kernel<<<7, 128>>>(qkvw, qkvb, gnb, gnw);
    gram_mma_kernel<<<dim3(7, GS, BATCH), 256, 98304>>>();
    sumG_kernel<<<1792, 256>>>();
    combineG_kernel<<<1024, 256>>>();
    headscores_kernel<<<dim3(64, BATCH), 256>>>();
    softmax_t_kernel<<<BATCH, 512>>>(gnw, outw, outb);
    egemm_kernel<<<dim3(4, 4, BATCH), 256>>>(outw);
    fgemm_kernel<<<dim3(2, HWN / 128, BATCH), 256, 65536>>>(x, out);
}